// round 1
// baseline (speedup 1.0000x reference)
#include <cuda_runtime.h>
#include <cstdint>

#define B_   32
#define C_   512
#define HW_  1024
#define C8_  64

// Scratch (allocation-free rule: device globals). ~80 MB total.
__device__ float g_q[(size_t)B_ * C8_ * HW_];   // [b][c8][hw]
__device__ float g_k[(size_t)B_ * C8_ * HW_];   // [b][c8][hw]
__device__ float g_v[(size_t)B_ * C_  * HW_];   // [b][c][hw]

// ---------------------------------------------------------------------------
// Kernel 1: fused QKV projection.
// Y[o, i] = sum_c W[o,c] * X[b,c,i] + bias[o], o in [0,640):
//   o <  64  -> q (wq, bq)
//   o < 128  -> k (wk, bk)
//   else     -> v (wv, bv)
// 128x128x8 register-blocked sgemm, 256 threads, 8x8 per thread.
// M=640 (5 tiles: tile0 = q+k, tiles1-4 = v), N=1024, K=512.
// ---------------------------------------------------------------------------
__global__ __launch_bounds__(256) void qkv_kernel(
    const float* __restrict__ x,
    const float* __restrict__ wq, const float* __restrict__ bq,
    const float* __restrict__ wk, const float* __restrict__ bk,
    const float* __restrict__ wv, const float* __restrict__ bv)
{
    const int b  = blockIdx.z;
    const int m0 = blockIdx.y * 128;
    const int n0 = blockIdx.x * 128;
    const int tid = threadIdx.x;
    const int tx = tid & 15;
    const int ty = tid >> 4;

    __shared__ float As[8][128];
    __shared__ float Bs[8][128];

    const float* X = x + (size_t)b * C_ * HW_;

    // A (weights) loader: k-contiguous rows -> transpose into As[k][m]
    const int arow = tid >> 1;            // 0..127 row within M tile
    const int acol = (tid & 1) * 4;       // 0 or 4 within BK
    const int o_ld = m0 + arow;
    const float* wrow;
    if (o_ld < 64)        wrow = wq + (size_t)o_ld * C_;
    else if (o_ld < 128)  wrow = wk + (size_t)(o_ld - 64) * C_;
    else                  wrow = wv + (size_t)(o_ld - 128) * C_;

    // B (X) loader: n-contiguous -> direct float4 into Bs[k][n]
    const int brow = tid >> 5;            // 0..7 (k)
    const int bcol = (tid & 31) * 4;      // 0..124 (n)

    float acc[8][8] = {};

    for (int k0 = 0; k0 < C_; k0 += 8) {
        float4 av = *reinterpret_cast<const float4*>(wrow + k0 + acol);
        float4 bv4 = *reinterpret_cast<const float4*>(
            X + (size_t)(k0 + brow) * HW_ + n0 + bcol);
        __syncthreads();
        As[acol + 0][arow] = av.x;
        As[acol + 1][arow] = av.y;
        As[acol + 2][arow] = av.z;
        As[acol + 3][arow] = av.w;
        *reinterpret_cast<float4*>(&Bs[brow][bcol]) = bv4;
        __syncthreads();
#pragma unroll
        for (int kk = 0; kk < 8; ++kk) {
            float a[8], bb[8];
            *(float4*)&a[0]  = *(const float4*)&As[kk][ty * 8];
            *(float4*)&a[4]  = *(const float4*)&As[kk][ty * 8 + 4];
            *(float4*)&bb[0] = *(const float4*)&Bs[kk][tx * 8];
            *(float4*)&bb[4] = *(const float4*)&Bs[kk][tx * 8 + 4];
#pragma unroll
            for (int i2 = 0; i2 < 8; ++i2)
#pragma unroll
                for (int j = 0; j < 8; ++j)
                    acc[i2][j] += a[i2] * bb[j];
        }
    }

#pragma unroll
    for (int i2 = 0; i2 < 8; ++i2) {
        const int oo = m0 + ty * 8 + i2;
        float bias;
        float* dst;
        if (oo < 64)        { bias = bq[oo];       dst = g_q + ((size_t)b * C8_ + oo)        * HW_; }
        else if (oo < 128)  { bias = bk[oo - 64];  dst = g_k + ((size_t)b * C8_ + (oo - 64)) * HW_; }
        else                { bias = bv[oo - 128]; dst = g_v + ((size_t)b * C_  + (oo - 128)) * HW_; }
        float4 o0, o1;
        o0.x = acc[i2][0] + bias; o0.y = acc[i2][1] + bias;
        o0.z = acc[i2][2] + bias; o0.w = acc[i2][3] + bias;
        o1.x = acc[i2][4] + bias; o1.y = acc[i2][5] + bias;
        o1.z = acc[i2][6] + bias; o1.w = acc[i2][7] + bias;
        *reinterpret_cast<float4*>(dst + n0 + tx * 8)     = o0;
        *reinterpret_cast<float4*>(dst + n0 + tx * 8 + 4) = o1;
    }
}

// ---------------------------------------------------------------------------
// Kernel 2a: energy[b,i,j] = sum_c q[b,c,i] * k[b,c,j]; M=N=1024, K=64.
// Both operands stored [c][pixel] (k-major) -> direct float4 smem loads.
// Writes raw energy into the attention output region (softmax'd in place next).
// ---------------------------------------------------------------------------
__global__ __launch_bounds__(256) void energy_kernel(float* __restrict__ att)
{
    const int b  = blockIdx.z;
    const int m0 = blockIdx.y * 128;   // i
    const int n0 = blockIdx.x * 128;   // j
    const int tid = threadIdx.x;
    const int tx = tid & 15;
    const int ty = tid >> 4;

    __shared__ float As[8][128];
    __shared__ float Bs[8][128];

    const float* Q  = g_q + (size_t)b * C8_ * HW_;
    const float* Kp = g_k + (size_t)b * C8_ * HW_;

    const int lrow = tid >> 5;          // 0..7 (k = c)
    const int lcol = (tid & 31) * 4;    // 0..124

    float acc[8][8] = {};

    for (int k0 = 0; k0 < C8_; k0 += 8) {
        float4 av = *reinterpret_cast<const float4*>(
            Q + (size_t)(k0 + lrow) * HW_ + m0 + lcol);
        float4 bv4 = *reinterpret_cast<const float4*>(
            Kp + (size_t)(k0 + lrow) * HW_ + n0 + lcol);
        __syncthreads();
        *reinterpret_cast<float4*>(&As[lrow][lcol]) = av;
        *reinterpret_cast<float4*>(&Bs[lrow][lcol]) = bv4;
        __syncthreads();
#pragma unroll
        for (int kk = 0; kk < 8; ++kk) {
            float a[8], bb[8];
            *(float4*)&a[0]  = *(const float4*)&As[kk][ty * 8];
            *(float4*)&a[4]  = *(const float4*)&As[kk][ty * 8 + 4];
            *(float4*)&bb[0] = *(const float4*)&Bs[kk][tx * 8];
            *(float4*)&bb[4] = *(const float4*)&Bs[kk][tx * 8 + 4];
#pragma unroll
            for (int i2 = 0; i2 < 8; ++i2)
#pragma unroll
                for (int j = 0; j < 8; ++j)
                    acc[i2][j] += a[i2] * bb[j];
        }
    }

    float* E = att + (size_t)b * HW_ * HW_;
#pragma unroll
    for (int i2 = 0; i2 < 8; ++i2) {
        float* row = E + (size_t)(m0 + ty * 8 + i2) * HW_ + n0 + tx * 8;
        *reinterpret_cast<float4*>(row)     = *(float4*)&acc[i2][0];
        *reinterpret_cast<float4*>(row + 4) = *(float4*)&acc[i2][4];
    }
}

// ---------------------------------------------------------------------------
// Kernel 2b: in-place row softmax over j (1024 elements per row).
// One block per row (32*1024 rows), 256 threads, one float4 per thread.
// ---------------------------------------------------------------------------
__global__ __launch_bounds__(256) void softmax_kernel(float* __restrict__ att)
{
    const size_t row = blockIdx.x;
    float4* p = reinterpret_cast<float4*>(att + row * HW_);
    float4 v = p[threadIdx.x];

    __shared__ float red[8];
    const int lid = threadIdx.x & 31;
    const int wid = threadIdx.x >> 5;

    // max reduce
    float m = fmaxf(fmaxf(v.x, v.y), fmaxf(v.z, v.w));
#pragma unroll
    for (int off = 16; off; off >>= 1)
        m = fmaxf(m, __shfl_xor_sync(0xFFFFFFFFu, m, off));
    if (lid == 0) red[wid] = m;
    __syncthreads();
    m = red[0];
#pragma unroll
    for (int w = 1; w < 8; ++w) m = fmaxf(m, red[w]);
    __syncthreads();   // before reusing red[]

    v.x = __expf(v.x - m);
    v.y = __expf(v.y - m);
    v.z = __expf(v.z - m);
    v.w = __expf(v.w - m);

    float s = v.x + v.y + v.z + v.w;
#pragma unroll
    for (int off = 16; off; off >>= 1)
        s += __shfl_xor_sync(0xFFFFFFFFu, s, off);
    if (lid == 0) red[wid] = s;
    __syncthreads();
    s = red[0];
#pragma unroll
    for (int w = 1; w < 8; ++w) s += red[w];

    const float inv = 1.0f / s;
    v.x *= inv; v.y *= inv; v.z *= inv; v.w *= inv;
    p[threadIdx.x] = v;
}

// ---------------------------------------------------------------------------
// Kernel 3: out[b,c,i] = sum_j v[b,c,j] * att[b,i,j], fused epilogue:
//   rgb = gamma*out + x; hha_out = gamma*out + hha.
// M=512 (c), N=1024 (i), K=1024 (j). Both operands j-contiguous -> transpose
// loads into k-major smem.
// ---------------------------------------------------------------------------
__global__ __launch_bounds__(256) void out_kernel(
    const float* __restrict__ att, const float* __restrict__ x,
    const float* __restrict__ hha, const float* __restrict__ gamma,
    float* __restrict__ rgb, float* __restrict__ hhaout)
{
    const int b  = blockIdx.z;
    const int m0 = blockIdx.y * 128;   // c
    const int n0 = blockIdx.x * 128;   // i
    const int tid = threadIdx.x;
    const int tx = tid & 15;
    const int ty = tid >> 4;

    __shared__ float As[8][128];
    __shared__ float Bs[8][128];

    const float* V = g_v + (size_t)b * C_ * HW_;     // [c][j]
    const float* A = att + (size_t)b * HW_ * HW_;    // [i][j]

    const int trow = tid >> 1;            // 0..127
    const int tcol = (tid & 1) * 4;       // 0 or 4

    float acc[8][8] = {};

    for (int k0 = 0; k0 < HW_; k0 += 8) {
        float4 av = *reinterpret_cast<const float4*>(
            V + (size_t)(m0 + trow) * HW_ + k0 + tcol);
        float4 bv4 = *reinterpret_cast<const float4*>(
            A + (size_t)(n0 + trow) * HW_ + k0 + tcol);
        __syncthreads();
        As[tcol + 0][trow] = av.x;
        As[tcol + 1][trow] = av.y;
        As[tcol + 2][trow] = av.z;
        As[tcol + 3][trow] = av.w;
        Bs[tcol + 0][trow] = bv4.x;
        Bs[tcol + 1][trow] = bv4.y;
        Bs[tcol + 2][trow] = bv4.z;
        Bs[tcol + 3][trow] = bv4.w;
        __syncthreads();
#pragma unroll
        for (int kk = 0; kk < 8; ++kk) {
            float a[8], bb[8];
            *(float4*)&a[0]  = *(const float4*)&As[kk][ty * 8];
            *(float4*)&a[4]  = *(const float4*)&As[kk][ty * 8 + 4];
            *(float4*)&bb[0] = *(const float4*)&Bs[kk][tx * 8];
            *(float4*)&bb[4] = *(const float4*)&Bs[kk][tx * 8 + 4];
#pragma unroll
            for (int i2 = 0; i2 < 8; ++i2)
#pragma unroll
                for (int j = 0; j < 8; ++j)
                    acc[i2][j] += a[i2] * bb[j];
        }
    }

    const float g = gamma[0];
#pragma unroll
    for (int i2 = 0; i2 < 8; ++i2) {
        const int c = m0 + ty * 8 + i2;
        const size_t base = ((size_t)b * C_ + c) * HW_ + n0 + tx * 8;
        float4 x0 = *reinterpret_cast<const float4*>(x + base);
        float4 x1 = *reinterpret_cast<const float4*>(x + base + 4);
        float4 h0 = *reinterpret_cast<const float4*>(hha + base);
        float4 h1 = *reinterpret_cast<const float4*>(hha + base + 4);
        float o[8];
#pragma unroll
        for (int j = 0; j < 8; ++j) o[j] = g * acc[i2][j];
        float4 r0, r1, q0, q1;
        r0.x = o[0] + x0.x; r0.y = o[1] + x0.y; r0.z = o[2] + x0.z; r0.w = o[3] + x0.w;
        r1.x = o[4] + x1.x; r1.y = o[5] + x1.y; r1.z = o[6] + x1.z; r1.w = o[7] + x1.w;
        q0.x = o[0] + h0.x; q0.y = o[1] + h0.y; q0.z = o[2] + h0.z; q0.w = o[3] + h0.w;
        q1.x = o[4] + h1.x; q1.y = o[5] + h1.y; q1.z = o[6] + h1.z; q1.w = o[7] + h1.w;
        *reinterpret_cast<float4*>(rgb + base)        = r0;
        *reinterpret_cast<float4*>(rgb + base + 4)    = r1;
        *reinterpret_cast<float4*>(hhaout + base)     = q0;
        *reinterpret_cast<float4*>(hhaout + base + 4) = q1;
    }
}

// ---------------------------------------------------------------------------
extern "C" void kernel_launch(void* const* d_in, const int* in_sizes, int n_in,
                              void* d_out, int out_size)
{
    const float* x     = (const float*)d_in[0];
    const float* hha   = (const float*)d_in[1];
    const float* wq    = (const float*)d_in[2];
    const float* bq    = (const float*)d_in[3];
    const float* wk    = (const float*)d_in[4];
    const float* bk    = (const float*)d_in[5];
    const float* wv    = (const float*)d_in[6];
    const float* bv    = (const float*)d_in[7];
    const float* gamma = (const float*)d_in[8];

    float* att    = (float*)d_out;                         // [32,1024,1024]
    float* rgb    = att + (size_t)B_ * HW_ * HW_;          // [32,512,32,32]
    float* hhaout = rgb + (size_t)B_ * C_ * HW_;           // [32,512,32,32]

    qkv_kernel    <<<dim3(8, 5, 32), 256>>>(x, wq, bq, wk, bk, wv, bv);
    energy_kernel <<<dim3(8, 8, 32), 256>>>(att);
    softmax_kernel<<<B_ * HW_, 256>>>(att);
    out_kernel    <<<dim3(8, 4, 32), 256>>>(att, x, hha, gamma, rgb, hhaout);
}

// round 3
// speedup vs baseline: 1.5584x; 1.5584x over previous
#include <cuda_runtime.h>
#include <cuda_bf16.h>
#include <cstdint>

#define B_   32
#define C_   512
#define HW_  1024
#define C8_  64

#if defined(__CUDA_ARCH__) && defined(__CUDA_ARCH_FEAT_SM103_ALL)
#define HAS_TCGEN05 1
#else
#define HAS_TCGEN05 0
#endif

// Scratch (allocation-free rule: device globals).
__device__ float g_q[(size_t)B_ * C8_ * HW_];   // [b][c8][hw]
__device__ float g_k[(size_t)B_ * C8_ * HW_];   // [b][c8][hw]
__device__ float g_v[(size_t)B_ * C_  * HW_];   // [b][c][hw]

// ---------------------------------------------------------------------------
// PTX helpers
// ---------------------------------------------------------------------------
__device__ __forceinline__ uint32_t smem_u32(const void* p) {
    uint32_t a;
    asm("{ .reg .u64 t; cvta.to.shared.u64 t, %1; cvt.u32.u64 %0, t; }" : "=r"(a) : "l"(p));
    return a;
}
__device__ __forceinline__ uint32_t elect_one_pred() {
    uint32_t p;
    asm volatile("{\n\t.reg .pred p;\n\telect.sync _|p, 0xFFFFFFFF;\n\tselp.b32 %0, 1, 0, p;\n\t}" : "=r"(p));
    return p;
}
#define SMEM_SWIZZLE_128B(off) ((off) ^ (((off) >> 3) & 0x70))

static constexpr uint64_t DESC_BASE_SW128 =
    (uint64_t(2) << 61) | (uint64_t(1) << 46) | (uint64_t(64) << 32) | (uint64_t(1) << 16);
__device__ __forceinline__ uint64_t make_desc(uint32_t addr) {
    return DESC_BASE_SW128 | ((uint64_t)(addr >> 4) & 0x3FFF);
}

__device__ __forceinline__ void mbar_init(uint32_t a, uint32_t cnt) {
    asm volatile("mbarrier.init.shared.b64 [%0], %1;" :: "r"(a), "r"(cnt) : "memory");
}
__device__ __forceinline__ void mbar_inval(uint32_t a) {
    asm volatile("mbarrier.inval.shared.b64 [%0];" :: "r"(a) : "memory");
}
__device__ __forceinline__ void mbar_wait(uint32_t a, uint32_t parity) {
    asm volatile(
        "{\n\t.reg .pred P;\n\t"
        "WL_%=:\n\t"
        "mbarrier.try_wait.parity.acquire.cta.shared::cta.b64 P, [%0], %1, 0x989680;\n\t"
        "@P bra.uni WD_%=;\n\t"
        "bra.uni WL_%=;\n\t"
        "WD_%=:\n\t}"
        :: "r"(a), "r"(parity) : "memory");
}

#if HAS_TCGEN05
// cg1 SS bf16 MMA (K=16 per issue): D[128,128] += A(desc) * B(desc)^T
__device__ __forceinline__ void mma_f16_ss(uint32_t d, uint64_t da, uint64_t db,
                                           uint32_t idesc, uint32_t en) {
    asm volatile(
        "{\n\t.reg .pred p;\n\tsetp.ne.u32 p, %4, 0;\n\t"
        "tcgen05.mma.cta_group::1.kind::f16 [%0], %1, %2, %3, {%5,%5,%5,%5}, p;\n\t}"
        :: "r"(d), "l"(da), "l"(db), "r"(idesc), "r"(en), "r"(0u) : "memory");
}
__device__ __forceinline__ void tc_commit(uint32_t mbar) {
    asm volatile("tcgen05.commit.cta_group::1.mbarrier::arrive::one.shared::cluster.b64 [%0];"
                 :: "r"(mbar) : "memory");
}
#define TCGEN05_LD_32X32B_X32(r, tmem_addr) \
    asm volatile( \
        "tcgen05.ld.sync.aligned.32x32b.x32.b32 " \
        "{%0, %1, %2, %3, %4, %5, %6, %7, " \
        " %8, %9, %10, %11, %12, %13, %14, %15, " \
        " %16, %17, %18, %19, %20, %21, %22, %23, " \
        " %24, %25, %26, %27, %28, %29, %30, %31}, [%32];" \
        : "=r"((r)[0]),  "=r"((r)[1]),  "=r"((r)[2]),  "=r"((r)[3]), \
          "=r"((r)[4]),  "=r"((r)[5]),  "=r"((r)[6]),  "=r"((r)[7]), \
          "=r"((r)[8]),  "=r"((r)[9]),  "=r"((r)[10]), "=r"((r)[11]), \
          "=r"((r)[12]), "=r"((r)[13]), "=r"((r)[14]), "=r"((r)[15]), \
          "=r"((r)[16]), "=r"((r)[17]), "=r"((r)[18]), "=r"((r)[19]), \
          "=r"((r)[20]), "=r"((r)[21]), "=r"((r)[22]), "=r"((r)[23]), \
          "=r"((r)[24]), "=r"((r)[25]), "=r"((r)[26]), "=r"((r)[27]), \
          "=r"((r)[28]), "=r"((r)[29]), "=r"((r)[30]), "=r"((r)[31]) \
        : "r"(tmem_addr))
#endif  // HAS_TCGEN05

// ---------------------------------------------------------------------------
// Kernel 1: fused QKV projection (fp32 SIMT).
// ---------------------------------------------------------------------------
__global__ __launch_bounds__(256) void qkv_kernel(
    const float* __restrict__ x,
    const float* __restrict__ wq, const float* __restrict__ bq,
    const float* __restrict__ wk, const float* __restrict__ bk,
    const float* __restrict__ wv, const float* __restrict__ bv)
{
    const int b  = blockIdx.z;
    const int m0 = blockIdx.y * 128;
    const int n0 = blockIdx.x * 128;
    const int tid = threadIdx.x;
    const int tx = tid & 15;
    const int ty = tid >> 4;

    __shared__ float As[8][128];
    __shared__ float Bs[8][128];

    const float* X = x + (size_t)b * C_ * HW_;

    const int arow = tid >> 1;
    const int acol = (tid & 1) * 4;
    const int o_ld = m0 + arow;
    const float* wrow;
    if (o_ld < 64)        wrow = wq + (size_t)o_ld * C_;
    else if (o_ld < 128)  wrow = wk + (size_t)(o_ld - 64) * C_;
    else                  wrow = wv + (size_t)(o_ld - 128) * C_;

    const int brow = tid >> 5;
    const int bcol = (tid & 31) * 4;

    float acc[8][8] = {};

    for (int k0 = 0; k0 < C_; k0 += 8) {
        float4 av = *reinterpret_cast<const float4*>(wrow + k0 + acol);
        float4 bv4 = *reinterpret_cast<const float4*>(
            X + (size_t)(k0 + brow) * HW_ + n0 + bcol);
        __syncthreads();
        As[acol + 0][arow] = av.x;
        As[acol + 1][arow] = av.y;
        As[acol + 2][arow] = av.z;
        As[acol + 3][arow] = av.w;
        *reinterpret_cast<float4*>(&Bs[brow][bcol]) = bv4;
        __syncthreads();
#pragma unroll
        for (int kk = 0; kk < 8; ++kk) {
            float a[8], bb[8];
            *(float4*)&a[0]  = *(const float4*)&As[kk][ty * 8];
            *(float4*)&a[4]  = *(const float4*)&As[kk][ty * 8 + 4];
            *(float4*)&bb[0] = *(const float4*)&Bs[kk][tx * 8];
            *(float4*)&bb[4] = *(const float4*)&Bs[kk][tx * 8 + 4];
#pragma unroll
            for (int i2 = 0; i2 < 8; ++i2)
#pragma unroll
                for (int j = 0; j < 8; ++j)
                    acc[i2][j] += a[i2] * bb[j];
        }
    }

#pragma unroll
    for (int i2 = 0; i2 < 8; ++i2) {
        const int oo = m0 + ty * 8 + i2;
        float bias;
        float* dst;
        if (oo < 64)        { bias = bq[oo];       dst = g_q + ((size_t)b * C8_ + oo)        * HW_; }
        else if (oo < 128)  { bias = bk[oo - 64];  dst = g_k + ((size_t)b * C8_ + (oo - 64)) * HW_; }
        else                { bias = bv[oo - 128]; dst = g_v + ((size_t)b * C_  + (oo - 128)) * HW_; }
        float4 o0, o1;
        o0.x = acc[i2][0] + bias; o0.y = acc[i2][1] + bias;
        o0.z = acc[i2][2] + bias; o0.w = acc[i2][3] + bias;
        o1.x = acc[i2][4] + bias; o1.y = acc[i2][5] + bias;
        o1.z = acc[i2][6] + bias; o1.w = acc[i2][7] + bias;
        *reinterpret_cast<float4*>(dst + n0 + tx * 8)     = o0;
        *reinterpret_cast<float4*>(dst + n0 + tx * 8 + 4) = o1;
    }
}

// ---------------------------------------------------------------------------
// Kernel 2a: energy (fp32 SIMT)
// ---------------------------------------------------------------------------
__global__ __launch_bounds__(256) void energy_kernel(float* __restrict__ att)
{
    const int b  = blockIdx.z;
    const int m0 = blockIdx.y * 128;
    const int n0 = blockIdx.x * 128;
    const int tid = threadIdx.x;
    const int tx = tid & 15;
    const int ty = tid >> 4;

    __shared__ float As[8][128];
    __shared__ float Bs[8][128];

    const float* Q  = g_q + (size_t)b * C8_ * HW_;
    const float* Kp = g_k + (size_t)b * C8_ * HW_;

    const int lrow = tid >> 5;
    const int lcol = (tid & 31) * 4;

    float acc[8][8] = {};

    for (int k0 = 0; k0 < C8_; k0 += 8) {
        float4 av = *reinterpret_cast<const float4*>(
            Q + (size_t)(k0 + lrow) * HW_ + m0 + lcol);
        float4 bv4 = *reinterpret_cast<const float4*>(
            Kp + (size_t)(k0 + lrow) * HW_ + n0 + lcol);
        __syncthreads();
        *reinterpret_cast<float4*>(&As[lrow][lcol]) = av;
        *reinterpret_cast<float4*>(&Bs[lrow][lcol]) = bv4;
        __syncthreads();
#pragma unroll
        for (int kk = 0; kk < 8; ++kk) {
            float a[8], bb[8];
            *(float4*)&a[0]  = *(const float4*)&As[kk][ty * 8];
            *(float4*)&a[4]  = *(const float4*)&As[kk][ty * 8 + 4];
            *(float4*)&bb[0] = *(const float4*)&Bs[kk][tx * 8];
            *(float4*)&bb[4] = *(const float4*)&Bs[kk][tx * 8 + 4];
#pragma unroll
            for (int i2 = 0; i2 < 8; ++i2)
#pragma unroll
                for (int j = 0; j < 8; ++j)
                    acc[i2][j] += a[i2] * bb[j];
        }
    }

    float* E = att + (size_t)b * HW_ * HW_;
#pragma unroll
    for (int i2 = 0; i2 < 8; ++i2) {
        float* row = E + (size_t)(m0 + ty * 8 + i2) * HW_ + n0 + tx * 8;
        *reinterpret_cast<float4*>(row)     = *(float4*)&acc[i2][0];
        *reinterpret_cast<float4*>(row + 4) = *(float4*)&acc[i2][4];
    }
}

// ---------------------------------------------------------------------------
// Kernel 2b: softmax
// ---------------------------------------------------------------------------
__global__ __launch_bounds__(256) void softmax_kernel(float* __restrict__ att)
{
    const size_t row = blockIdx.x;
    float4* p = reinterpret_cast<float4*>(att + row * HW_);
    float4 v = p[threadIdx.x];

    __shared__ float red[8];
    const int lid = threadIdx.x & 31;
    const int wid = threadIdx.x >> 5;

    float m = fmaxf(fmaxf(v.x, v.y), fmaxf(v.z, v.w));
#pragma unroll
    for (int off = 16; off; off >>= 1)
        m = fmaxf(m, __shfl_xor_sync(0xFFFFFFFFu, m, off));
    if (lid == 0) red[wid] = m;
    __syncthreads();
    m = red[0];
#pragma unroll
    for (int w = 1; w < 8; ++w) m = fmaxf(m, red[w]);
    __syncthreads();

    v.x = __expf(v.x - m);
    v.y = __expf(v.y - m);
    v.z = __expf(v.z - m);
    v.w = __expf(v.w - m);

    float s = v.x + v.y + v.z + v.w;
#pragma unroll
    for (int off = 16; off; off >>= 1)
        s += __shfl_xor_sync(0xFFFFFFFFu, s, off);
    if (lid == 0) red[wid] = s;
    __syncthreads();
    s = red[0];
#pragma unroll
    for (int w = 1; w < 8; ++w) s += red[w];

    const float inv = 1.0f / s;
    v.x *= inv; v.y *= inv; v.z *= inv; v.w *= inv;
    p[threadIdx.x] = v;
}

// ---------------------------------------------------------------------------
// Kernel 3: out GEMM. tcgen05 bf16x3 path for sm_103a; SIMT fallback for the
// plain sm_103 compilation pass (never expected to run on GB300).
// D[c,i] = sum_j V[c,j]*Att[i,j]; epilogue rgb = g*D + x; hha_out = g*D + hha.
// ---------------------------------------------------------------------------
static constexpr uint32_t OUT_IDESC =
    (1u << 4) | (1u << 7) | (1u << 10) | ((128u / 8) << 17) | ((128u / 16) << 24);

static constexpr int STAGE_BYTES = 65536;           // Ahi,Alo,Bhi,Blo x 16KB
static constexpr int TILE_BYTES  = 16384;           // 128 rows x 128B
static constexpr int OUT_SMEM    = 1024 + 2 * STAGE_BYTES;

__device__ __forceinline__ void split8(float4 a, float4 b, uint4& hi, uint4& lo)
{
    float v[8] = {a.x, a.y, a.z, a.w, b.x, b.y, b.z, b.w};
    uint32_t h[4], l[4];
#pragma unroll
    for (int i = 0; i < 4; ++i) {
        float v0 = v[2 * i], v1 = v[2 * i + 1];
        uint32_t hp;
        asm("cvt.rn.bf16x2.f32 %0, %1, %2;" : "=r"(hp) : "f"(v1), "f"(v0));
        float f0 = __uint_as_float(hp << 16);
        float f1 = __uint_as_float(hp & 0xFFFF0000u);
        float r0 = v0 - f0;
        float r1 = v1 - f1;
        uint32_t lp;
        asm("cvt.rn.bf16x2.f32 %0, %1, %2;" : "=r"(lp) : "f"(r1), "f"(r0));
        h[i] = hp; l[i] = lp;
    }
    hi = make_uint4(h[0], h[1], h[2], h[3]);
    lo = make_uint4(l[0], l[1], l[2], l[3]);
}

__global__ __launch_bounds__(256)
void out_tc_kernel(const float* __restrict__ att, const float* __restrict__ x,
                   const float* __restrict__ hha, const float* __restrict__ gamma,
                   float* __restrict__ rgb, float* __restrict__ hhaout)
{
    extern __shared__ char smem[];
    const int tid = threadIdx.x;
    const int b  = blockIdx.z;
    const int m0 = blockIdx.y * 128;   // channels
    const int n0 = blockIdx.x * 128;   // pixels

#if HAS_TCGEN05
    const uint32_t sb = smem_u32(smem);

    // TMEM alloc (128 cols for D) — warp 0
    if (tid < 32) {
        asm volatile("tcgen05.alloc.cta_group::1.sync.aligned.shared::cta.b32 [%0], %1;"
                     :: "r"(sb), "r"(128u) : "memory");
    }
    if (tid == 0) { mbar_init(sb + 8, 1); mbar_init(sb + 16, 1); }
    __syncthreads();
    const uint32_t tmem = *reinterpret_cast<volatile uint32_t*>(smem);

    const float* Vv  = g_v + (size_t)b * C_  * HW_;
    const float* Att = att + (size_t)b * HW_ * HW_;

    // loader mapping: 64 rows/pass (2 passes), 4 threads per row, 64B each
    const int lr = tid >> 2;             // 0..63
    const int lc = (tid & 3) * 16;       // fp32 col base (0,16,32,48)

    for (int k = 0; k < 16; ++k) {
        const int s = k & 1;
        if (k >= 2) {
            const int j = k >> 1;
            mbar_wait(sb + 8 + s * 8, (uint32_t)((j - 1) & 1));
        }
        const int k0 = k * 64;
        char* stg = smem + 1024 + s * STAGE_BYTES;
#pragma unroll
        for (int pass = 0; pass < 2; ++pass) {
            const int r = lr + pass * 64;
            const float* Ar = Vv  + (size_t)(m0 + r) * HW_ + k0 + lc;
            const float* Br = Att + (size_t)(n0 + r) * HW_ + k0 + lc;
#pragma unroll
            for (int h = 0; h < 2; ++h) {
                const uint32_t sw = SMEM_SWIZZLE_128B((uint32_t)(r * 128 + (lc + h * 8) * 2));
                float4 a0 = *reinterpret_cast<const float4*>(Ar + h * 8);
                float4 a1 = *reinterpret_cast<const float4*>(Ar + h * 8 + 4);
                uint4 hi, lo;
                split8(a0, a1, hi, lo);
                *reinterpret_cast<uint4*>(stg + sw)              = hi;   // A hi
                *reinterpret_cast<uint4*>(stg + TILE_BYTES + sw) = lo;   // A lo
                float4 b0 = *reinterpret_cast<const float4*>(Br + h * 8);
                float4 b1 = *reinterpret_cast<const float4*>(Br + h * 8 + 4);
                split8(b0, b1, hi, lo);
                *reinterpret_cast<uint4*>(stg + 2 * TILE_BYTES + sw) = hi;  // B hi
                *reinterpret_cast<uint4*>(stg + 3 * TILE_BYTES + sw) = lo;  // B lo
            }
        }
        asm volatile("fence.proxy.async.shared::cta;" ::: "memory");
        __syncthreads();

        if (tid < 32 && elect_one_pred()) {
            const uint32_t su = sb + 1024 + s * STAGE_BYTES;
            const uint64_t dAh = make_desc(su);
            const uint64_t dAl = make_desc(su + TILE_BYTES);
            const uint64_t dBh = make_desc(su + 2 * TILE_BYTES);
            const uint64_t dBl = make_desc(su + 3 * TILE_BYTES);
#pragma unroll
            for (int ks = 0; ks < 4; ++ks) {
                const uint32_t en0 = (k == 0 && ks == 0) ? 0u : 1u;
                mma_f16_ss(tmem, dAh + ks * 2, dBh + ks * 2, OUT_IDESC, en0);
                mma_f16_ss(tmem, dAh + ks * 2, dBl + ks * 2, OUT_IDESC, 1u);
                mma_f16_ss(tmem, dAl + ks * 2, dBh + ks * 2, OUT_IDESC, 1u);
            }
            tc_commit(sb + 8 + s * 8);
        }
    }

    // drain both stages (8 commits each -> last completes phase parity 1)
    mbar_wait(sb + 8, 1u);
    mbar_wait(sb + 16, 1u);
    asm volatile("tcgen05.fence::after_thread_sync;" ::: "memory");
    __syncthreads();

    // Epilogue: read D (fp32) 32 cols at a time, transpose via SMEM, fused write.
    const float g = gamma[0];
    float* ep = reinterpret_cast<float*>(smem + 1024);
    const size_t obase = ((size_t)b * C_ + m0) * HW_ + n0;

    for (int cb = 0; cb < 128; cb += 32) {
        if (tid < 128) {
            uint32_t dreg[32];
            TCGEN05_LD_32X32B_X32(dreg, tmem + cb);
            asm volatile("tcgen05.wait::ld.sync.aligned;" ::: "memory");
#pragma unroll
            for (int c = 0; c < 32; ++c)
                ep[tid * 33 + c] = __uint_as_float(dreg[c]);
        }
        __syncthreads();
#pragma unroll
        for (int it = 0; it < 16; ++it) {
            const int idx = it * 256 + tid;
            const int m = idx >> 5;
            const int c = idx & 31;
            const float o = g * ep[m * 33 + c];
            const size_t gb = obase + (size_t)m * HW_ + cb + c;
            rgb[gb]    = o + x[gb];
            hhaout[gb] = o + hha[gb];
        }
        __syncthreads();
    }

    if (tid == 0) { mbar_inval(sb + 8); mbar_inval(sb + 16); }
    if (tid < 32) {
        asm volatile("tcgen05.relinquish_alloc_permit.cta_group::1.sync.aligned;" ::: "memory");
        asm volatile("tcgen05.dealloc.cta_group::1.sync.aligned.b32 %0, %1;"
                     :: "r"(tmem), "r"(128u));
    }
#else
    // -------- SIMT fallback (compiled for plain sm_103 pass; correct, slower) --
    const int tx = tid & 15;
    const int ty = tid >> 4;

    float (*As)[128] = reinterpret_cast<float(*)[128]>(smem);
    float (*Bs)[128] = reinterpret_cast<float(*)[128]>(smem + 8 * 128 * 4);

    const float* V = g_v + (size_t)b * C_ * HW_;
    const float* A = att + (size_t)b * HW_ * HW_;

    const int trow = tid >> 1;
    const int tcol = (tid & 1) * 4;

    float acc[8][8] = {};

    for (int k0 = 0; k0 < HW_; k0 += 8) {
        float4 av = *reinterpret_cast<const float4*>(
            V + (size_t)(m0 + trow) * HW_ + k0 + tcol);
        float4 bv4 = *reinterpret_cast<const float4*>(
            A + (size_t)(n0 + trow) * HW_ + k0 + tcol);
        __syncthreads();
        As[tcol + 0][trow] = av.x;
        As[tcol + 1][trow] = av.y;
        As[tcol + 2][trow] = av.z;
        As[tcol + 3][trow] = av.w;
        Bs[tcol + 0][trow] = bv4.x;
        Bs[tcol + 1][trow] = bv4.y;
        Bs[tcol + 2][trow] = bv4.z;
        Bs[tcol + 3][trow] = bv4.w;
        __syncthreads();
#pragma unroll
        for (int kk = 0; kk < 8; ++kk) {
            float a[8], bb[8];
            *(float4*)&a[0]  = *(const float4*)&As[kk][ty * 8];
            *(float4*)&a[4]  = *(const float4*)&As[kk][ty * 8 + 4];
            *(float4*)&bb[0] = *(const float4*)&Bs[kk][tx * 8];
            *(float4*)&bb[4] = *(const float4*)&Bs[kk][tx * 8 + 4];
#pragma unroll
            for (int i2 = 0; i2 < 8; ++i2)
#pragma unroll
                for (int j = 0; j < 8; ++j)
                    acc[i2][j] += a[i2] * bb[j];
        }
    }

    const float g = gamma[0];
#pragma unroll
    for (int i2 = 0; i2 < 8; ++i2) {
        const int c = m0 + ty * 8 + i2;
        const size_t base = ((size_t)b * C_ + c) * HW_ + n0 + tx * 8;
#pragma unroll
        for (int j = 0; j < 8; ++j) {
            const float o = g * acc[i2][j];
            rgb[base + j]    = o + x[base + j];
            hhaout[base + j] = o + hha[base + j];
        }
    }
#endif
}

// ---------------------------------------------------------------------------
extern "C" void kernel_launch(void* const* d_in, const int* in_sizes, int n_in,
                              void* d_out, int out_size)
{
    const float* x     = (const float*)d_in[0];
    const float* hha   = (const float*)d_in[1];
    const float* wq    = (const float*)d_in[2];
    const float* bq    = (const float*)d_in[3];
    const float* wk    = (const float*)d_in[4];
    const float* bk    = (const float*)d_in[5];
    const float* wv    = (const float*)d_in[6];
    const float* bv    = (const float*)d_in[7];
    const float* gamma = (const float*)d_in[8];

    float* att    = (float*)d_out;                         // [32,1024,1024]
    float* rgb    = att + (size_t)B_ * HW_ * HW_;          // [32,512,32,32]
    float* hhaout = rgb + (size_t)B_ * C_ * HW_;           // [32,512,32,32]

    static bool attr_set = false;
    if (!attr_set) {
        cudaFuncSetAttribute(out_tc_kernel, cudaFuncAttributeMaxDynamicSharedMemorySize, OUT_SMEM);
        attr_set = true;
    }

    qkv_kernel    <<<dim3(8, 5, 32), 256>>>(x, wq, bq, wk, bk, wv, bv);
    energy_kernel <<<dim3(8, 8, 32), 256>>>(att);
    softmax_kernel<<<B_ * HW_, 256>>>(att);
    out_tc_kernel <<<dim3(8, 4, 32), 256, OUT_SMEM>>>(att, x, hha, gamma, rgb, hhaout);
}

// round 4
// speedup vs baseline: 2.3644x; 1.5172x over previous
#include <cuda_runtime.h>
#include <cuda_bf16.h>
#include <cstdint>

#define B_    32
#define C_    512
#define HW_   1024
#define C8_   64
#define WR_   640     // 64 q + 64 k + 512 v rows

#if defined(__CUDA_ARCH__) && defined(__CUDA_ARCH_FEAT_SM103_ALL)
#define HAS_TCGEN05 1
#else
#define HAS_TCGEN05 0
#endif

// ---------------------------------------------------------------------------
// Scratch (device globals; ~340MB total)
// ---------------------------------------------------------------------------
__device__ __nv_bfloat16 g_xT_hi[(size_t)B_ * HW_ * C_];   // [b][i][c]
__device__ __nv_bfloat16 g_xT_lo[(size_t)B_ * HW_ * C_];
__device__ __nv_bfloat16 g_w_hi [(size_t)WR_ * C_];        // [o][c]
__device__ __nv_bfloat16 g_w_lo [(size_t)WR_ * C_];
__device__ __nv_bfloat16 g_qT_hi[(size_t)B_ * HW_ * C8_];  // [b][i][c8]
__device__ __nv_bfloat16 g_qT_lo[(size_t)B_ * HW_ * C8_];
__device__ __nv_bfloat16 g_kT_hi[(size_t)B_ * HW_ * C8_];
__device__ __nv_bfloat16 g_kT_lo[(size_t)B_ * HW_ * C8_];
__device__ __nv_bfloat16 g_v_hi [(size_t)B_ * C_ * HW_];   // [c][j]
__device__ __nv_bfloat16 g_v_lo [(size_t)B_ * C_ * HW_];
__device__ __nv_bfloat16 g_att_hi[(size_t)B_ * HW_ * HW_]; // [i][j]
__device__ __nv_bfloat16 g_att_lo[(size_t)B_ * HW_ * HW_];

// ---------------------------------------------------------------------------
// Helpers
// ---------------------------------------------------------------------------
__device__ __forceinline__ uint32_t smem_u32(const void* p) {
    uint32_t a;
    asm("{ .reg .u64 t; cvta.to.shared.u64 t, %1; cvt.u32.u64 %0, t; }" : "=r"(a) : "l"(p));
    return a;
}
__device__ __forceinline__ uint32_t elect_one_pred() {
    uint32_t p;
    asm volatile("{\n\t.reg .pred p;\n\telect.sync _|p, 0xFFFFFFFF;\n\tselp.b32 %0, 1, 0, p;\n\t}" : "=r"(p));
    return p;
}
#define SMEM_SWIZZLE_128B(off) ((off) ^ (((off) >> 3) & 0x70))

// pack two fp32 -> bf16x2 (hi) and residual bf16x2 (lo)
__device__ __forceinline__ void split2(float a, float b, uint32_t& hi, uint32_t& lo) {
    asm("cvt.rn.bf16x2.f32 %0, %1, %2;" : "=r"(hi) : "f"(b), "f"(a));
    float fa = __uint_as_float(hi << 16);
    float fb = __uint_as_float(hi & 0xFFFF0000u);
    asm("cvt.rn.bf16x2.f32 %0, %1, %2;" : "=r"(lo) : "f"(b - fb), "f"(a - fa));
}
__device__ __forceinline__ void split1(float v, __nv_bfloat16& h, __nv_bfloat16& l) {
    h = __float2bfloat16(v);
    l = __float2bfloat16(v - __bfloat162float(h));
}
__device__ __forceinline__ float recon(const __nv_bfloat16* h, const __nv_bfloat16* l, size_t i) {
    return __bfloat162float(h[i]) + __bfloat162float(l[i]);
}

static constexpr uint64_t DESC_BASE_SW128 =
    (uint64_t(2) << 61) | (uint64_t(1) << 46) | (uint64_t(64) << 32) | (uint64_t(1) << 16);
__device__ __forceinline__ uint64_t make_desc(uint32_t addr) {
    return DESC_BASE_SW128 | ((uint64_t)(addr >> 4) & 0x3FFF);
}
__device__ __forceinline__ void mbar_init(uint32_t a, uint32_t cnt) {
    asm volatile("mbarrier.init.shared.b64 [%0], %1;" :: "r"(a), "r"(cnt) : "memory");
}
__device__ __forceinline__ void mbar_inval(uint32_t a) {
    asm volatile("mbarrier.inval.shared.b64 [%0];" :: "r"(a) : "memory");
}
__device__ __forceinline__ void mbar_wait(uint32_t a, uint32_t parity) {
    asm volatile(
        "{\n\t.reg .pred P;\n\t"
        "WL_%=:\n\t"
        "mbarrier.try_wait.parity.acquire.cta.shared::cta.b64 P, [%0], %1, 0x989680;\n\t"
        "@P bra.uni WD_%=;\n\t"
        "bra.uni WL_%=;\n\t"
        "WD_%=:\n\t}"
        :: "r"(a), "r"(parity) : "memory");
}

static constexpr uint32_t IDESC_128x128 =
    (1u << 4) | (1u << 7) | (1u << 10) | ((128u / 8) << 17) | ((128u / 16) << 24);
static constexpr int TILE_BYTES  = 16384;          // 128 rows x 128B
static constexpr int STAGE_BYTES = 4 * TILE_BYTES; // Ahi,Alo,Bhi,Blo
static constexpr int PIPE_SMEM   = 1024 + 2 * STAGE_BYTES;   // 132096
static constexpr int ONESHOT_SMEM = 1024 + STAGE_BYTES;      // 66560

#if HAS_TCGEN05
__device__ __forceinline__ void mma_f16_ss(uint32_t d, uint64_t da, uint64_t db,
                                           uint32_t idesc, uint32_t en) {
    asm volatile(
        "{\n\t.reg .pred p;\n\tsetp.ne.u32 p, %4, 0;\n\t"
        "tcgen05.mma.cta_group::1.kind::f16 [%0], %1, %2, %3, {%5,%5,%5,%5}, p;\n\t}"
        :: "r"(d), "l"(da), "l"(db), "r"(idesc), "r"(en), "r"(0u) : "memory");
}
__device__ __forceinline__ void tc_commit(uint32_t mbar) {
    asm volatile("tcgen05.commit.cta_group::1.mbarrier::arrive::one.shared::cluster.b64 [%0];"
                 :: "r"(mbar) : "memory");
}
__device__ __forceinline__ void tc_alloc(uint32_t smem_addr, uint32_t cols) {
    asm volatile("tcgen05.alloc.cta_group::1.sync.aligned.shared::cta.b32 [%0], %1;"
                 :: "r"(smem_addr), "r"(cols) : "memory");
}
__device__ __forceinline__ void tc_dealloc(uint32_t tmem, uint32_t cols) {
    asm volatile("tcgen05.relinquish_alloc_permit.cta_group::1.sync.aligned;" ::: "memory");
    asm volatile("tcgen05.dealloc.cta_group::1.sync.aligned.b32 %0, %1;" :: "r"(tmem), "r"(cols));
}
#define TCGEN05_LD_32X32B_X32(r, tmem_addr) \
    asm volatile( \
        "tcgen05.ld.sync.aligned.32x32b.x32.b32 " \
        "{%0, %1, %2, %3, %4, %5, %6, %7, " \
        " %8, %9, %10, %11, %12, %13, %14, %15, " \
        " %16, %17, %18, %19, %20, %21, %22, %23, " \
        " %24, %25, %26, %27, %28, %29, %30, %31}, [%32];" \
        : "=r"((r)[0]),  "=r"((r)[1]),  "=r"((r)[2]),  "=r"((r)[3]), \
          "=r"((r)[4]),  "=r"((r)[5]),  "=r"((r)[6]),  "=r"((r)[7]), \
          "=r"((r)[8]),  "=r"((r)[9]),  "=r"((r)[10]), "=r"((r)[11]), \
          "=r"((r)[12]), "=r"((r)[13]), "=r"((r)[14]), "=r"((r)[15]), \
          "=r"((r)[16]), "=r"((r)[17]), "=r"((r)[18]), "=r"((r)[19]), \
          "=r"((r)[20]), "=r"((r)[21]), "=r"((r)[22]), "=r"((r)[23]), \
          "=r"((r)[24]), "=r"((r)[25]), "=r"((r)[26]), "=r"((r)[27]), \
          "=r"((r)[28]), "=r"((r)[29]), "=r"((r)[30]), "=r"((r)[31]) \
        : "r"(tmem_addr))
#endif

// ---------------------------------------------------------------------------
// Prep 1: transpose + split x [b][c][i] fp32 -> xT_hi/lo [b][i][c] bf16
// ---------------------------------------------------------------------------
__global__ void xsplit_kernel(const float* __restrict__ x)
{
    __shared__ float t[32][33];
    const int b  = blockIdx.z;
    const int i0 = blockIdx.x * 32;
    const int c0 = blockIdx.y * 32;
    const int tx = threadIdx.x, ty = threadIdx.y;

#pragma unroll
    for (int j = 0; j < 4; ++j)
        t[ty + 8 * j][tx] = x[((size_t)b * C_ + c0 + ty + 8 * j) * HW_ + i0 + tx];
    __syncthreads();
#pragma unroll
    for (int j = 0; j < 4; ++j) {
        const int c = c0 + tx;
        const int i = i0 + ty + 8 * j;
        const float f = t[tx][ty + 8 * j];
        __nv_bfloat16 h, l;
        split1(f, h, l);
        const size_t idx = ((size_t)b * HW_ + i) * C_ + c;
        g_xT_hi[idx] = h;
        g_xT_lo[idx] = l;
    }
}

// ---------------------------------------------------------------------------
// Prep 2: split weights into combined [640][512] bf16 hi/lo
// ---------------------------------------------------------------------------
__global__ void wsplit_kernel(const float* __restrict__ wq,
                              const float* __restrict__ wk,
                              const float* __restrict__ wv)
{
    const int idx = blockIdx.x * 256 + threadIdx.x;   // < 640*512
    const int o = idx >> 9;
    const int c = idx & 511;
    float v;
    if (o < 64)        v = wq[(size_t)o * C_ + c];
    else if (o < 128)  v = wk[(size_t)(o - 64) * C_ + c];
    else               v = wv[(size_t)(o - 128) * C_ + c];
    __nv_bfloat16 h, l;
    split1(v, h, l);
    g_w_hi[idx] = h;
    g_w_lo[idx] = l;
}

// ---------------------------------------------------------------------------
// Kernel: QKV projection on tcgen05 (bf16x3).
// Y[o,i] = sum_c W[o,c] xT[i,c] + bias; M=640 (5 tiles), N=1024, K=512.
// m-tile 0 -> q (rows 0-63, transposed out) + k (rows 64-127, transposed out)
// m-tiles 1-4 -> v (bf16 hi/lo out, [c][j])
// ---------------------------------------------------------------------------
__global__ __launch_bounds__(256) void qkv_tc_kernel(
    const float* __restrict__ bq, const float* __restrict__ bk,
    const float* __restrict__ bv)
{
    extern __shared__ char smem[];
    const int tid = threadIdx.x;
    const int b   = blockIdx.z;
    const int mt  = blockIdx.y;
    const int m0  = mt * 128;
    const int n0  = blockIdx.x * 128;

#if HAS_TCGEN05
    const uint32_t sb = smem_u32(smem);
    if (tid < 32) tc_alloc(sb, 128u);
    if (tid == 0) { mbar_init(sb + 8, 1); mbar_init(sb + 16, 1); }
    __syncthreads();
    const uint32_t tmem = *reinterpret_cast<volatile uint32_t*>(smem);

    const int lr = tid >> 1;
    const int ec = (tid & 1) * 32;
    const __nv_bfloat16* wh = g_w_hi + (size_t)(m0 + lr) * C_;
    const __nv_bfloat16* wl = g_w_lo + (size_t)(m0 + lr) * C_;
    const __nv_bfloat16* xh = g_xT_hi + ((size_t)b * HW_ + n0 + lr) * C_;
    const __nv_bfloat16* xl = g_xT_lo + ((size_t)b * HW_ + n0 + lr) * C_;

    for (int k = 0; k < 8; ++k) {
        const int s = k & 1;
        if (k >= 2) mbar_wait(sb + 8 + s * 8, (uint32_t)(((k >> 1) - 1) & 1));
        const int k0 = k * 64;
        char* stg = smem + 1024 + s * STAGE_BYTES;
#pragma unroll
        for (int h = 0; h < 4; ++h) {
            const int e = ec + h * 8;
            const uint32_t sw = SMEM_SWIZZLE_128B((uint32_t)(lr * 128 + e * 2));
            *reinterpret_cast<uint4*>(stg + sw)                  = *reinterpret_cast<const uint4*>(wh + k0 + e);
            *reinterpret_cast<uint4*>(stg + TILE_BYTES + sw)     = *reinterpret_cast<const uint4*>(wl + k0 + e);
            *reinterpret_cast<uint4*>(stg + 2 * TILE_BYTES + sw) = *reinterpret_cast<const uint4*>(xh + k0 + e);
            *reinterpret_cast<uint4*>(stg + 3 * TILE_BYTES + sw) = *reinterpret_cast<const uint4*>(xl + k0 + e);
        }
        asm volatile("fence.proxy.async.shared::cta;" ::: "memory");
        __syncthreads();
        if (tid < 32 && elect_one_pred()) {
            const uint32_t su = sb + 1024 + s * STAGE_BYTES;
            const uint64_t dAh = make_desc(su);
            const uint64_t dAl = make_desc(su + TILE_BYTES);
            const uint64_t dBh = make_desc(su + 2 * TILE_BYTES);
            const uint64_t dBl = make_desc(su + 3 * TILE_BYTES);
#pragma unroll
            for (int ks = 0; ks < 4; ++ks) {
                const uint32_t en0 = (k == 0 && ks == 0) ? 0u : 1u;
                mma_f16_ss(tmem, dAh + ks * 2, dBh + ks * 2, IDESC_128x128, en0);
                mma_f16_ss(tmem, dAh + ks * 2, dBl + ks * 2, IDESC_128x128, 1u);
                mma_f16_ss(tmem, dAl + ks * 2, dBh + ks * 2, IDESC_128x128, 1u);
            }
            tc_commit(sb + 8 + s * 8);
        }
    }
    mbar_wait(sb + 8, 1u);    // 4 commits/stage -> final phase 3, parity 1
    mbar_wait(sb + 16, 1u);
    asm volatile("tcgen05.fence::after_thread_sync;" ::: "memory");
    __syncthreads();

    if (mt == 0) {
        // q (rows 0-63) and k (rows 64-127): transposed bf16 hi/lo out
        float* ep = reinterpret_cast<float*>(smem + 1024);
        for (int cb = 0; cb < 128; cb += 32) {
            if (tid < 128) {
                uint32_t d[32];
                TCGEN05_LD_32X32B_X32(d, tmem + cb);
                asm volatile("tcgen05.wait::ld.sync.aligned;" ::: "memory");
                const float bias = (tid < 64) ? bq[tid] : bk[tid - 64];
#pragma unroll
                for (int c = 0; c < 32; ++c)
                    ep[tid * 33 + c] = __uint_as_float(d[c]) + bias;
            }
            __syncthreads();
            const int il = tid >> 3;          // 0..31 local i
            const int ob = (tid & 7) * 8;     // 0..56 row-base within 64
            {   // q
                uint32_t hi[4], lo[4];
#pragma unroll
                for (int e = 0; e < 4; ++e)
                    split2(ep[(ob + 2 * e) * 33 + il], ep[(ob + 2 * e + 1) * 33 + il], hi[e], lo[e]);
                const size_t qi = ((size_t)b * HW_ + n0 + cb + il) * C8_ + ob;
                *reinterpret_cast<uint4*>(g_qT_hi + qi) = make_uint4(hi[0], hi[1], hi[2], hi[3]);
                *reinterpret_cast<uint4*>(g_qT_lo + qi) = make_uint4(lo[0], lo[1], lo[2], lo[3]);
            }
            {   // k
                uint32_t hi[4], lo[4];
#pragma unroll
                for (int e = 0; e < 4; ++e)
                    split2(ep[(64 + ob + 2 * e) * 33 + il], ep[(64 + ob + 2 * e + 1) * 33 + il], hi[e], lo[e]);
                const size_t ki = ((size_t)b * HW_ + n0 + cb + il) * C8_ + ob;
                *reinterpret_cast<uint4*>(g_kT_hi + ki) = make_uint4(hi[0], hi[1], hi[2], hi[3]);
                *reinterpret_cast<uint4*>(g_kT_lo + ki) = make_uint4(lo[0], lo[1], lo[2], lo[3]);
            }
            __syncthreads();
        }
    } else {
        // v rows: bf16 hi/lo, direct (thread = channel row, 32 j contiguous)
        if (tid < 128) {
            const int c = m0 - 128 + tid;
            const float bias = bv[c];
            for (int cb = 0; cb < 128; cb += 32) {
                uint32_t d[32];
                TCGEN05_LD_32X32B_X32(d, tmem + cb);
                asm volatile("tcgen05.wait::ld.sync.aligned;" ::: "memory");
                uint32_t hi[16], lo[16];
#pragma unroll
                for (int e = 0; e < 16; ++e)
                    split2(__uint_as_float(d[2 * e]) + bias, __uint_as_float(d[2 * e + 1]) + bias,
                           hi[e], lo[e]);
                const size_t base = ((size_t)b * C_ + c) * HW_ + n0 + cb;
                uint4* dh = reinterpret_cast<uint4*>(g_v_hi + base);
                uint4* dl = reinterpret_cast<uint4*>(g_v_lo + base);
#pragma unroll
                for (int e = 0; e < 4; ++e) {
                    dh[e] = make_uint4(hi[4 * e], hi[4 * e + 1], hi[4 * e + 2], hi[4 * e + 3]);
                    dl[e] = make_uint4(lo[4 * e], lo[4 * e + 1], lo[4 * e + 2], lo[4 * e + 3]);
                }
            }
        }
    }
    __syncthreads();
    if (tid == 0) { mbar_inval(sb + 8); mbar_inval(sb + 16); }
    if (tid < 32) tc_dealloc(tmem, 128u);
#else
    // SIMT fallback (plain sm_103 pass only)
    for (int e = tid; e < 128 * 128; e += 256) {
        const int ml = e >> 7, nl = e & 127;
        const int o = m0 + ml, i = n0 + nl;
        float acc = 0.f;
        for (int c = 0; c < C_; ++c)
            acc += recon(g_w_hi, g_w_lo, (size_t)o * C_ + c) *
                   recon(g_xT_hi, g_xT_lo, ((size_t)b * HW_ + i) * C_ + c);
        __nv_bfloat16 h, l;
        if (o < 64) {
            split1(acc + bq[o], h, l);
            const size_t qi = ((size_t)b * HW_ + i) * C8_ + o;
            g_qT_hi[qi] = h; g_qT_lo[qi] = l;
        } else if (o < 128) {
            split1(acc + bk[o - 64], h, l);
            const size_t ki = ((size_t)b * HW_ + i) * C8_ + (o - 64);
            g_kT_hi[ki] = h; g_kT_lo[ki] = l;
        } else {
            split1(acc + bv[o - 128], h, l);
            const size_t vi = ((size_t)b * C_ + (o - 128)) * HW_ + i;
            g_v_hi[vi] = h; g_v_lo[vi] = l;
        }
    }
#endif
}

// ---------------------------------------------------------------------------
// Kernel: energy on tcgen05 (bf16x3). E[i,j] = sum_c q[i,c] k[j,c]. K=64.
// ---------------------------------------------------------------------------
__global__ __launch_bounds__(256) void energy_tc_kernel(float* __restrict__ att)
{
    extern __shared__ char smem[];
    const int tid = threadIdx.x;
    const int b  = blockIdx.z;
    const int m0 = blockIdx.y * 128;   // i
    const int n0 = blockIdx.x * 128;   // j

#if HAS_TCGEN05
    const uint32_t sb = smem_u32(smem);
    if (tid < 32) tc_alloc(sb, 128u);
    if (tid == 0) mbar_init(sb + 8, 1);
    __syncthreads();
    const uint32_t tmem = *reinterpret_cast<volatile uint32_t*>(smem);

    const int lr = tid >> 1;
    const int ec = (tid & 1) * 32;
    char* stg = smem + 1024;
    const __nv_bfloat16* qh = g_qT_hi + ((size_t)b * HW_ + m0 + lr) * C8_;
    const __nv_bfloat16* ql = g_qT_lo + ((size_t)b * HW_ + m0 + lr) * C8_;
    const __nv_bfloat16* kh = g_kT_hi + ((size_t)b * HW_ + n0 + lr) * C8_;
    const __nv_bfloat16* kl = g_kT_lo + ((size_t)b * HW_ + n0 + lr) * C8_;
#pragma unroll
    for (int h = 0; h < 4; ++h) {
        const int e = ec + h * 8;
        const uint32_t sw = SMEM_SWIZZLE_128B((uint32_t)(lr * 128 + e * 2));
        *reinterpret_cast<uint4*>(stg + sw)                  = *reinterpret_cast<const uint4*>(qh + e);
        *reinterpret_cast<uint4*>(stg + TILE_BYTES + sw)     = *reinterpret_cast<const uint4*>(ql + e);
        *reinterpret_cast<uint4*>(stg + 2 * TILE_BYTES + sw) = *reinterpret_cast<const uint4*>(kh + e);
        *reinterpret_cast<uint4*>(stg + 3 * TILE_BYTES + sw) = *reinterpret_cast<const uint4*>(kl + e);
    }
    asm volatile("fence.proxy.async.shared::cta;" ::: "memory");
    __syncthreads();

    if (tid < 32 && elect_one_pred()) {
        const uint32_t su = sb + 1024;
        const uint64_t dAh = make_desc(su);
        const uint64_t dAl = make_desc(su + TILE_BYTES);
        const uint64_t dBh = make_desc(su + 2 * TILE_BYTES);
        const uint64_t dBl = make_desc(su + 3 * TILE_BYTES);
#pragma unroll
        for (int ks = 0; ks < 4; ++ks) {
            mma_f16_ss(tmem, dAh + ks * 2, dBh + ks * 2, IDESC_128x128, ks == 0 ? 0u : 1u);
            mma_f16_ss(tmem, dAh + ks * 2, dBl + ks * 2, IDESC_128x128, 1u);
            mma_f16_ss(tmem, dAl + ks * 2, dBh + ks * 2, IDESC_128x128, 1u);
        }
        tc_commit(sb + 8);
    }
    mbar_wait(sb + 8, 0u);
    asm volatile("tcgen05.fence::after_thread_sync;" ::: "memory");

    if (tid < 128) {
        float* row = att + ((size_t)b * HW_ + m0 + tid) * HW_ + n0;
        for (int cb = 0; cb < 128; cb += 32) {
            uint32_t d[32];
            TCGEN05_LD_32X32B_X32(d, tmem + cb);
            asm volatile("tcgen05.wait::ld.sync.aligned;" ::: "memory");
            float4* dst = reinterpret_cast<float4*>(row + cb);
#pragma unroll
            for (int e = 0; e < 8; ++e)
                dst[e] = make_float4(__uint_as_float(d[4 * e]),     __uint_as_float(d[4 * e + 1]),
                                     __uint_as_float(d[4 * e + 2]), __uint_as_float(d[4 * e + 3]));
        }
    }
    __syncthreads();
    if (tid == 0) mbar_inval(sb + 8);
    if (tid < 32) tc_dealloc(tmem, 128u);
#else
    for (int e = tid; e < 128 * 128; e += 256) {
        const int ml = e >> 7, nl = e & 127;
        float acc = 0.f;
        for (int c = 0; c < C8_; ++c)
            acc += recon(g_qT_hi, g_qT_lo, ((size_t)b * HW_ + m0 + ml) * C8_ + c) *
                   recon(g_kT_hi, g_kT_lo, ((size_t)b * HW_ + n0 + nl) * C8_ + c);
        att[((size_t)b * HW_ + m0 + ml) * HW_ + n0 + nl] = acc;
    }
#endif
}

// ---------------------------------------------------------------------------
// Softmax (in place) + emit att_hi/att_lo bf16 for the out GEMM.
// ---------------------------------------------------------------------------
__global__ __launch_bounds__(256) void softmax_kernel(float* __restrict__ att)
{
    const size_t row = blockIdx.x;
    float4* p = reinterpret_cast<float4*>(att + row * HW_);
    float4 v = p[threadIdx.x];

    __shared__ float red[8];
    const int lid = threadIdx.x & 31;
    const int wid = threadIdx.x >> 5;

    float m = fmaxf(fmaxf(v.x, v.y), fmaxf(v.z, v.w));
#pragma unroll
    for (int off = 16; off; off >>= 1)
        m = fmaxf(m, __shfl_xor_sync(0xFFFFFFFFu, m, off));
    if (lid == 0) red[wid] = m;
    __syncthreads();
    m = red[0];
#pragma unroll
    for (int w = 1; w < 8; ++w) m = fmaxf(m, red[w]);
    __syncthreads();

    v.x = __expf(v.x - m);
    v.y = __expf(v.y - m);
    v.z = __expf(v.z - m);
    v.w = __expf(v.w - m);

    float s = v.x + v.y + v.z + v.w;
#pragma unroll
    for (int off = 16; off; off >>= 1)
        s += __shfl_xor_sync(0xFFFFFFFFu, s, off);
    if (lid == 0) red[wid] = s;
    __syncthreads();
    s = red[0];
#pragma unroll
    for (int w = 1; w < 8; ++w) s += red[w];

    const float inv = 1.0f / s;
    v.x *= inv; v.y *= inv; v.z *= inv; v.w *= inv;
    p[threadIdx.x] = v;

    uint32_t h0, l0, h1, l1;
    split2(v.x, v.y, h0, l0);
    split2(v.z, v.w, h1, l1);
    const size_t e = row * HW_ + (size_t)threadIdx.x * 4;
    *reinterpret_cast<uint2*>(g_att_hi + e) = make_uint2(h0, h1);
    *reinterpret_cast<uint2*>(g_att_lo + e) = make_uint2(l0, l1);
}

// ---------------------------------------------------------------------------
// Kernel: out GEMM on tcgen05 (bf16x3, preconverted operands).
// D[c,i] = sum_j V[c,j] Att[i,j]; rgb = g*D + x; hha_out = g*D + hha.
// ---------------------------------------------------------------------------
__global__ __launch_bounds__(256)
void out_tc_kernel(const float* __restrict__ x,
                   const float* __restrict__ hha, const float* __restrict__ gamma,
                   float* __restrict__ rgb, float* __restrict__ hhaout)
{
    extern __shared__ char smem[];
    const int tid = threadIdx.x;
    const int b  = blockIdx.z;
    const int m0 = blockIdx.y * 128;   // channels
    const int n0 = blockIdx.x * 128;   // pixels

#if HAS_TCGEN05
    const uint32_t sb = smem_u32(smem);
    if (tid < 32) tc_alloc(sb, 128u);
    if (tid == 0) { mbar_init(sb + 8, 1); mbar_init(sb + 16, 1); }
    __syncthreads();
    const uint32_t tmem = *reinterpret_cast<volatile uint32_t*>(smem);

    const int lr = tid >> 1;
    const int ec = (tid & 1) * 32;
    const __nv_bfloat16* vh = g_v_hi  + ((size_t)b * C_  + m0 + lr) * HW_;
    const __nv_bfloat16* vl = g_v_lo  + ((size_t)b * C_  + m0 + lr) * HW_;
    const __nv_bfloat16* ah = g_att_hi + ((size_t)b * HW_ + n0 + lr) * HW_;
    const __nv_bfloat16* al = g_att_lo + ((size_t)b * HW_ + n0 + lr) * HW_;

    for (int k = 0; k < 16; ++k) {
        const int s = k & 1;
        if (k >= 2) mbar_wait(sb + 8 + s * 8, (uint32_t)(((k >> 1) - 1) & 1));
        const int k0 = k * 64;
        char* stg = smem + 1024 + s * STAGE_BYTES;
#pragma unroll
        for (int h = 0; h < 4; ++h) {
            const int e = ec + h * 8;
            const uint32_t sw = SMEM_SWIZZLE_128B((uint32_t)(lr * 128 + e * 2));
            *reinterpret_cast<uint4*>(stg + sw)                  = *reinterpret_cast<const uint4*>(vh + k0 + e);
            *reinterpret_cast<uint4*>(stg + TILE_BYTES + sw)     = *reinterpret_cast<const uint4*>(vl + k0 + e);
            *reinterpret_cast<uint4*>(stg + 2 * TILE_BYTES + sw) = *reinterpret_cast<const uint4*>(ah + k0 + e);
            *reinterpret_cast<uint4*>(stg + 3 * TILE_BYTES + sw) = *reinterpret_cast<const uint4*>(al + k0 + e);
        }
        asm volatile("fence.proxy.async.shared::cta;" ::: "memory");
        __syncthreads();
        if (tid < 32 && elect_one_pred()) {
            const uint32_t su = sb + 1024 + s * STAGE_BYTES;
            const uint64_t dAh = make_desc(su);
            const uint64_t dAl = make_desc(su + TILE_BYTES);
            const uint64_t dBh = make_desc(su + 2 * TILE_BYTES);
            const uint64_t dBl = make_desc(su + 3 * TILE_BYTES);
#pragma unroll
            for (int ks = 0; ks < 4; ++ks) {
                const uint32_t en0 = (k == 0 && ks == 0) ? 0u : 1u;
                mma_f16_ss(tmem, dAh + ks * 2, dBh + ks * 2, IDESC_128x128, en0);
                mma_f16_ss(tmem, dAh + ks * 2, dBl + ks * 2, IDESC_128x128, 1u);
                mma_f16_ss(tmem, dAl + ks * 2, dBh + ks * 2, IDESC_128x128, 1u);
            }
            tc_commit(sb + 8 + s * 8);
        }
    }
    mbar_wait(sb + 8, 1u);
    mbar_wait(sb + 16, 1u);
    asm volatile("tcgen05.fence::after_thread_sync;" ::: "memory");
    __syncthreads();

    const float g = gamma[0];
    float* ep = reinterpret_cast<float*>(smem + 1024);
    const size_t obase = ((size_t)b * C_ + m0) * HW_ + n0;

    for (int cb = 0; cb < 128; cb += 32) {
        if (tid < 128) {
            uint32_t d[32];
            TCGEN05_LD_32X32B_X32(d, tmem + cb);
            asm volatile("tcgen05.wait::ld.sync.aligned;" ::: "memory");
#pragma unroll
            for (int c = 0; c < 32; ++c)
                ep[tid * 33 + c] = __uint_as_float(d[c]);
        }
        __syncthreads();
#pragma unroll
        for (int it = 0; it < 16; ++it) {
            const int idx = it * 256 + tid;
            const int mm = idx >> 5;
            const int c  = idx & 31;
            const float o = g * ep[mm * 33 + c];
            const size_t gb = obase + (size_t)mm * HW_ + cb + c;
            rgb[gb]    = o + x[gb];
            hhaout[gb] = o + hha[gb];
        }
        __syncthreads();
    }

    if (tid == 0) { mbar_inval(sb + 8); mbar_inval(sb + 16); }
    if (tid < 32) tc_dealloc(tmem, 128u);
#else
    const float g = gamma[0];
    for (int e = tid; e < 128 * 128; e += 256) {
        const int ml = e >> 7, nl = e & 127;
        float acc = 0.f;
        for (int j = 0; j < HW_; ++j)
            acc += recon(g_v_hi, g_v_lo, ((size_t)b * C_ + m0 + ml) * HW_ + j) *
                   recon(g_att_hi, g_att_lo, ((size_t)b * HW_ + n0 + nl) * HW_ + j);
        const size_t gb = ((size_t)b * C_ + m0 + ml) * HW_ + n0 + nl;
        rgb[gb]    = g * acc + x[gb];
        hhaout[gb] = g * acc + hha[gb];
    }
#endif
}

// ---------------------------------------------------------------------------
extern "C" void kernel_launch(void* const* d_in, const int* in_sizes, int n_in,
                              void* d_out, int out_size)
{
    const float* x     = (const float*)d_in[0];
    const float* hha   = (const float*)d_in[1];
    const float* wq    = (const float*)d_in[2];
    const float* bq    = (const float*)d_in[3];
    const float* wk    = (const float*)d_in[4];
    const float* bk    = (const float*)d_in[5];
    const float* wv    = (const float*)d_in[6];
    const float* bv    = (const float*)d_in[7];
    const float* gamma = (const float*)d_in[8];

    float* att    = (float*)d_out;                         // [32,1024,1024]
    float* rgb    = att + (size_t)B_ * HW_ * HW_;          // [32,512,32,32]
    float* hhaout = rgb + (size_t)B_ * C_ * HW_;           // [32,512,32,32]

    static bool attr_set = false;
    if (!attr_set) {
        cudaFuncSetAttribute(qkv_tc_kernel,    cudaFuncAttributeMaxDynamicSharedMemorySize, PIPE_SMEM);
        cudaFuncSetAttribute(energy_tc_kernel, cudaFuncAttributeMaxDynamicSharedMemorySize, ONESHOT_SMEM);
        cudaFuncSetAttribute(out_tc_kernel,    cudaFuncAttributeMaxDynamicSharedMemorySize, PIPE_SMEM);
        attr_set = true;
    }

    xsplit_kernel   <<<dim3(32, 16, 32), dim3(32, 8)>>>(x);
    wsplit_kernel   <<<WR_ * C_ / 256, 256>>>(wq, wk, wv);
    qkv_tc_kernel   <<<dim3(8, 5, 32), 256, PIPE_SMEM>>>(bq, bk, bv);
    energy_tc_kernel<<<dim3(8, 8, 32), 256, ONESHOT_SMEM>>>(att);
    softmax_kernel  <<<B_ * HW_, 256>>>(att);
    out_tc_kernel   <<<dim3(8, 4, 32), 256, PIPE_SMEM>>>(x, hha, gamma, rgb, hhaout);
}

// round 5
// speedup vs baseline: 2.9995x; 1.2686x over previous
#include <cuda_runtime.h>
#include <cuda_bf16.h>
#include <cstdint>

#define B_    32
#define C_    512
#define HW_   1024
#define C8_   64
#define WR_   640     // 64 q + 64 k + 512 v rows

#if defined(__CUDA_ARCH__) && defined(__CUDA_ARCH_FEAT_SM103_ALL)
#define HAS_TCGEN05 1
#else
#define HAS_TCGEN05 0
#endif

// ---------------------------------------------------------------------------
// Scratch (device globals)
// ---------------------------------------------------------------------------
__device__ __nv_bfloat16 g_xT_hi[(size_t)B_ * HW_ * C_];   // [b][i][c]
__device__ __nv_bfloat16 g_xT_lo[(size_t)B_ * HW_ * C_];
__device__ __nv_bfloat16 g_w_hi [(size_t)WR_ * C_];        // [o][c]
__device__ __nv_bfloat16 g_w_lo [(size_t)WR_ * C_];
__device__ __nv_bfloat16 g_qT_hi[(size_t)B_ * HW_ * C8_];  // [b][i][c8]
__device__ __nv_bfloat16 g_qT_lo[(size_t)B_ * HW_ * C8_];
__device__ __nv_bfloat16 g_kT_hi[(size_t)B_ * HW_ * C8_];
__device__ __nv_bfloat16 g_kT_lo[(size_t)B_ * HW_ * C8_];
__device__ __nv_bfloat16 g_v_hi [(size_t)B_ * C_ * HW_];   // [c][j]
__device__ __nv_bfloat16 g_v_lo [(size_t)B_ * C_ * HW_];
__device__ __nv_bfloat16 g_att_hi[(size_t)B_ * HW_ * HW_]; // [i][j]
__device__ __nv_bfloat16 g_att_lo[(size_t)B_ * HW_ * HW_];

// ---------------------------------------------------------------------------
// Helpers
// ---------------------------------------------------------------------------
__device__ __forceinline__ uint32_t smem_u32(const void* p) {
    uint32_t a;
    asm("{ .reg .u64 t; cvta.to.shared.u64 t, %1; cvt.u32.u64 %0, t; }" : "=r"(a) : "l"(p));
    return a;
}
__device__ __forceinline__ uint32_t elect_one_pred() {
    uint32_t p;
    asm volatile("{\n\t.reg .pred p;\n\telect.sync _|p, 0xFFFFFFFF;\n\tselp.b32 %0, 1, 0, p;\n\t}" : "=r"(p));
    return p;
}
#define SMEM_SWIZZLE_128B(off) ((off) ^ (((off) >> 3) & 0x70))

__device__ __forceinline__ void cp16(uint32_t dst, const void* src) {
    asm volatile("cp.async.cg.shared.global [%0], [%1], 16;" :: "r"(dst), "l"(src));
}
__device__ __forceinline__ void cp_commit() {
    asm volatile("cp.async.commit_group;" ::: "memory");
}

// pack two fp32 -> bf16x2 (hi) and residual bf16x2 (lo)
__device__ __forceinline__ void split2(float a, float b, uint32_t& hi, uint32_t& lo) {
    asm("cvt.rn.bf16x2.f32 %0, %1, %2;" : "=r"(hi) : "f"(b), "f"(a));
    float fa = __uint_as_float(hi << 16);
    float fb = __uint_as_float(hi & 0xFFFF0000u);
    asm("cvt.rn.bf16x2.f32 %0, %1, %2;" : "=r"(lo) : "f"(b - fb), "f"(a - fa));
}
__device__ __forceinline__ void split1(float v, __nv_bfloat16& h, __nv_bfloat16& l) {
    h = __float2bfloat16(v);
    l = __float2bfloat16(v - __bfloat162float(h));
}
__device__ __forceinline__ float recon(const __nv_bfloat16* h, const __nv_bfloat16* l, size_t i) {
    return __bfloat162float(h[i]) + __bfloat162float(l[i]);
}

static constexpr uint64_t DESC_BASE_SW128 =
    (uint64_t(2) << 61) | (uint64_t(1) << 46) | (uint64_t(64) << 32) | (uint64_t(1) << 16);
__device__ __forceinline__ uint64_t make_desc(uint32_t addr) {
    return DESC_BASE_SW128 | ((uint64_t)(addr >> 4) & 0x3FFF);
}
__device__ __forceinline__ void mbar_init(uint32_t a, uint32_t cnt) {
    asm volatile("mbarrier.init.shared.b64 [%0], %1;" :: "r"(a), "r"(cnt) : "memory");
}
__device__ __forceinline__ void mbar_inval(uint32_t a) {
    asm volatile("mbarrier.inval.shared.b64 [%0];" :: "r"(a) : "memory");
}
__device__ __forceinline__ void mbar_wait(uint32_t a, uint32_t parity) {
    asm volatile(
        "{\n\t.reg .pred P;\n\t"
        "WL_%=:\n\t"
        "mbarrier.try_wait.parity.acquire.cta.shared::cta.b64 P, [%0], %1, 0x989680;\n\t"
        "@P bra.uni WD_%=;\n\t"
        "bra.uni WL_%=;\n\t"
        "WD_%=:\n\t}"
        :: "r"(a), "r"(parity) : "memory");
}

static constexpr uint32_t IDESC_128x128 =
    (1u << 4) | (1u << 7) | (1u << 10) | ((128u / 8) << 17) | ((128u / 16) << 24);
static constexpr uint32_t IDESC_128x256 =
    (1u << 4) | (1u << 7) | (1u << 10) | ((256u / 8) << 17) | ((128u / 16) << 24);

static constexpr int TILE_BYTES  = 16384;           // 128 rows x 128B
static constexpr int QKV_STAGE   = 4 * TILE_BYTES;  // Ahi,Alo,Bhi,Blo
static constexpr int QKV_SMEM    = 1024 + 2 * QKV_STAGE;        // 132096
static constexpr int EN_SMEM     = 1024 + 2 * TILE_BYTES + 2 * 32768;   // 99328
static constexpr int OUT_STAGE   = 2 * 32768 + 2 * TILE_BYTES;  // A(256r) hi/lo + B(128r) hi/lo = 96KB
static constexpr int OUT_SMEM    = 1024 + 2 * OUT_STAGE;        // 197632

#if HAS_TCGEN05
__device__ __forceinline__ void mma_f16_ss(uint32_t d, uint64_t da, uint64_t db,
                                           uint32_t idesc, uint32_t en) {
    asm volatile(
        "{\n\t.reg .pred p;\n\tsetp.ne.u32 p, %4, 0;\n\t"
        "tcgen05.mma.cta_group::1.kind::f16 [%0], %1, %2, %3, {%5,%5,%5,%5}, p;\n\t}"
        :: "r"(d), "l"(da), "l"(db), "r"(idesc), "r"(en), "r"(0u) : "memory");
}
__device__ __forceinline__ void tc_commit(uint32_t mbar) {
    asm volatile("tcgen05.commit.cta_group::1.mbarrier::arrive::one.shared::cluster.b64 [%0];"
                 :: "r"(mbar) : "memory");
}
__device__ __forceinline__ void tc_alloc(uint32_t smem_addr, uint32_t cols) {
    asm volatile("tcgen05.alloc.cta_group::1.sync.aligned.shared::cta.b32 [%0], %1;"
                 :: "r"(smem_addr), "r"(cols) : "memory");
}
__device__ __forceinline__ void tc_dealloc(uint32_t tmem, uint32_t cols) {
    asm volatile("tcgen05.relinquish_alloc_permit.cta_group::1.sync.aligned;" ::: "memory");
    asm volatile("tcgen05.dealloc.cta_group::1.sync.aligned.b32 %0, %1;" :: "r"(tmem), "r"(cols));
}
#define TCGEN05_LD_32X32B_X32(r, tmem_addr) \
    asm volatile( \
        "tcgen05.ld.sync.aligned.32x32b.x32.b32 " \
        "{%0, %1, %2, %3, %4, %5, %6, %7, " \
        " %8, %9, %10, %11, %12, %13, %14, %15, " \
        " %16, %17, %18, %19, %20, %21, %22, %23, " \
        " %24, %25, %26, %27, %28, %29, %30, %31}, [%32];" \
        : "=r"((r)[0]),  "=r"((r)[1]),  "=r"((r)[2]),  "=r"((r)[3]), \
          "=r"((r)[4]),  "=r"((r)[5]),  "=r"((r)[6]),  "=r"((r)[7]), \
          "=r"((r)[8]),  "=r"((r)[9]),  "=r"((r)[10]), "=r"((r)[11]), \
          "=r"((r)[12]), "=r"((r)[13]), "=r"((r)[14]), "=r"((r)[15]), \
          "=r"((r)[16]), "=r"((r)[17]), "=r"((r)[18]), "=r"((r)[19]), \
          "=r"((r)[20]), "=r"((r)[21]), "=r"((r)[22]), "=r"((r)[23]), \
          "=r"((r)[24]), "=r"((r)[25]), "=r"((r)[26]), "=r"((r)[27]), \
          "=r"((r)[28]), "=r"((r)[29]), "=r"((r)[30]), "=r"((r)[31]) \
        : "r"(tmem_addr))
#endif

// ---------------------------------------------------------------------------
// Prep 1: transpose + split x [b][c][i] fp32 -> xT_hi/lo [b][i][c] bf16
// ---------------------------------------------------------------------------
__global__ void xsplit_kernel(const float* __restrict__ x)
{
    __shared__ float t[32][33];
    const int b  = blockIdx.z;
    const int i0 = blockIdx.x * 32;
    const int c0 = blockIdx.y * 32;
    const int tx = threadIdx.x, ty = threadIdx.y;

#pragma unroll
    for (int j = 0; j < 4; ++j)
        t[ty + 8 * j][tx] = x[((size_t)b * C_ + c0 + ty + 8 * j) * HW_ + i0 + tx];
    __syncthreads();
#pragma unroll
    for (int j = 0; j < 4; ++j) {
        const int c = c0 + tx;
        const int i = i0 + ty + 8 * j;
        const float f = t[tx][ty + 8 * j];
        __nv_bfloat16 h, l;
        split1(f, h, l);
        const size_t idx = ((size_t)b * HW_ + i) * C_ + c;
        g_xT_hi[idx] = h;
        g_xT_lo[idx] = l;
    }
}

// ---------------------------------------------------------------------------
// Prep 2: split weights into combined [640][512] bf16 hi/lo
// ---------------------------------------------------------------------------
__global__ void wsplit_kernel(const float* __restrict__ wq,
                              const float* __restrict__ wk,
                              const float* __restrict__ wv)
{
    const int idx = blockIdx.x * 256 + threadIdx.x;   // < 640*512
    const int o = idx >> 9;
    const int c = idx & 511;
    float v;
    if (o < 64)        v = wq[(size_t)o * C_ + c];
    else if (o < 128)  v = wk[(size_t)(o - 64) * C_ + c];
    else               v = wv[(size_t)(o - 128) * C_ + c];
    __nv_bfloat16 h, l;
    split1(v, h, l);
    g_w_hi[idx] = h;
    g_w_lo[idx] = l;
}

// ---------------------------------------------------------------------------
// Kernel: QKV projection on tcgen05 (bf16x3). Unchanged from R4 (passing).
// ---------------------------------------------------------------------------
__global__ __launch_bounds__(256) void qkv_tc_kernel(
    const float* __restrict__ bq, const float* __restrict__ bk,
    const float* __restrict__ bv)
{
    extern __shared__ char smem[];
    const int tid = threadIdx.x;
    const int b   = blockIdx.z;
    const int mt  = blockIdx.y;
    const int m0  = mt * 128;
    const int n0  = blockIdx.x * 128;

#if HAS_TCGEN05
    const uint32_t sb = smem_u32(smem);
    if (tid < 32) tc_alloc(sb, 128u);
    if (tid == 0) { mbar_init(sb + 8, 1); mbar_init(sb + 16, 1); }
    __syncthreads();
    const uint32_t tmem = *reinterpret_cast<volatile uint32_t*>(smem);

    const int lr = tid >> 1;
    const int ec = (tid & 1) * 32;
    const __nv_bfloat16* wh = g_w_hi + (size_t)(m0 + lr) * C_;
    const __nv_bfloat16* wl = g_w_lo + (size_t)(m0 + lr) * C_;
    const __nv_bfloat16* xh = g_xT_hi + ((size_t)b * HW_ + n0 + lr) * C_;
    const __nv_bfloat16* xl = g_xT_lo + ((size_t)b * HW_ + n0 + lr) * C_;

    for (int k = 0; k < 8; ++k) {
        const int s = k & 1;
        if (k >= 2) mbar_wait(sb + 8 + s * 8, (uint32_t)(((k >> 1) - 1) & 1));
        const int k0 = k * 64;
        char* stg = smem + 1024 + s * QKV_STAGE;
#pragma unroll
        for (int h = 0; h < 4; ++h) {
            const int e = ec + h * 8;
            const uint32_t sw = SMEM_SWIZZLE_128B((uint32_t)(lr * 128 + e * 2));
            *reinterpret_cast<uint4*>(stg + sw)                  = *reinterpret_cast<const uint4*>(wh + k0 + e);
            *reinterpret_cast<uint4*>(stg + TILE_BYTES + sw)     = *reinterpret_cast<const uint4*>(wl + k0 + e);
            *reinterpret_cast<uint4*>(stg + 2 * TILE_BYTES + sw) = *reinterpret_cast<const uint4*>(xh + k0 + e);
            *reinterpret_cast<uint4*>(stg + 3 * TILE_BYTES + sw) = *reinterpret_cast<const uint4*>(xl + k0 + e);
        }
        asm volatile("fence.proxy.async.shared::cta;" ::: "memory");
        __syncthreads();
        if (tid < 32 && elect_one_pred()) {
            const uint32_t su = sb + 1024 + s * QKV_STAGE;
            const uint64_t dAh = make_desc(su);
            const uint64_t dAl = make_desc(su + TILE_BYTES);
            const uint64_t dBh = make_desc(su + 2 * TILE_BYTES);
            const uint64_t dBl = make_desc(su + 3 * TILE_BYTES);
#pragma unroll
            for (int ks = 0; ks < 4; ++ks) {
                const uint32_t en0 = (k == 0 && ks == 0) ? 0u : 1u;
                mma_f16_ss(tmem, dAh + ks * 2, dBh + ks * 2, IDESC_128x128, en0);
                mma_f16_ss(tmem, dAh + ks * 2, dBl + ks * 2, IDESC_128x128, 1u);
                mma_f16_ss(tmem, dAl + ks * 2, dBh + ks * 2, IDESC_128x128, 1u);
            }
            tc_commit(sb + 8 + s * 8);
        }
    }
    mbar_wait(sb + 8, 1u);
    mbar_wait(sb + 16, 1u);
    asm volatile("tcgen05.fence::after_thread_sync;" ::: "memory");
    __syncthreads();

    if (mt == 0) {
        float* ep = reinterpret_cast<float*>(smem + 1024);
        for (int cb = 0; cb < 128; cb += 32) {
            if (tid < 128) {
                uint32_t d[32];
                TCGEN05_LD_32X32B_X32(d, tmem + cb);
                asm volatile("tcgen05.wait::ld.sync.aligned;" ::: "memory");
                const float bias = (tid < 64) ? bq[tid] : bk[tid - 64];
#pragma unroll
                for (int c = 0; c < 32; ++c)
                    ep[tid * 33 + c] = __uint_as_float(d[c]) + bias;
            }
            __syncthreads();
            const int il = tid >> 3;
            const int ob = (tid & 7) * 8;
            {   // q
                uint32_t hi[4], lo[4];
#pragma unroll
                for (int e = 0; e < 4; ++e)
                    split2(ep[(ob + 2 * e) * 33 + il], ep[(ob + 2 * e + 1) * 33 + il], hi[e], lo[e]);
                const size_t qi = ((size_t)b * HW_ + n0 + cb + il) * C8_ + ob;
                *reinterpret_cast<uint4*>(g_qT_hi + qi) = make_uint4(hi[0], hi[1], hi[2], hi[3]);
                *reinterpret_cast<uint4*>(g_qT_lo + qi) = make_uint4(lo[0], lo[1], lo[2], lo[3]);
            }
            {   // k
                uint32_t hi[4], lo[4];
#pragma unroll
                for (int e = 0; e < 4; ++e)
                    split2(ep[(64 + ob + 2 * e) * 33 + il], ep[(64 + ob + 2 * e + 1) * 33 + il], hi[e], lo[e]);
                const size_t ki = ((size_t)b * HW_ + n0 + cb + il) * C8_ + ob;
                *reinterpret_cast<uint4*>(g_kT_hi + ki) = make_uint4(hi[0], hi[1], hi[2], hi[3]);
                *reinterpret_cast<uint4*>(g_kT_lo + ki) = make_uint4(lo[0], lo[1], lo[2], lo[3]);
            }
            __syncthreads();
        }
    } else {
        if (tid < 128) {
            const int c = m0 - 128 + tid;
            const float bias = bv[c];
            for (int cb = 0; cb < 128; cb += 32) {
                uint32_t d[32];
                TCGEN05_LD_32X32B_X32(d, tmem + cb);
                asm volatile("tcgen05.wait::ld.sync.aligned;" ::: "memory");
                uint32_t hi[16], lo[16];
#pragma unroll
                for (int e = 0; e < 16; ++e)
                    split2(__uint_as_float(d[2 * e]) + bias, __uint_as_float(d[2 * e + 1]) + bias,
                           hi[e], lo[e]);
                const size_t base = ((size_t)b * C_ + c) * HW_ + n0 + cb;
                uint4* dh = reinterpret_cast<uint4*>(g_v_hi + base);
                uint4* dl = reinterpret_cast<uint4*>(g_v_lo + base);
#pragma unroll
                for (int e = 0; e < 4; ++e) {
                    dh[e] = make_uint4(hi[4 * e], hi[4 * e + 1], hi[4 * e + 2], hi[4 * e + 3]);
                    dl[e] = make_uint4(lo[4 * e], lo[4 * e + 1], lo[4 * e + 2], lo[4 * e + 3]);
                }
            }
        }
    }
    __syncthreads();
    if (tid == 0) { mbar_inval(sb + 8); mbar_inval(sb + 16); }
    if (tid < 32) tc_dealloc(tmem, 128u);
#else
    for (int e = tid; e < 128 * 128; e += 256) {
        const int ml = e >> 7, nl = e & 127;
        const int o = m0 + ml, i = n0 + nl;
        float acc = 0.f;
        for (int c = 0; c < C_; ++c)
            acc += recon(g_w_hi, g_w_lo, (size_t)o * C_ + c) *
                   recon(g_xT_hi, g_xT_lo, ((size_t)b * HW_ + i) * C_ + c);
        __nv_bfloat16 h, l;
        if (o < 64) {
            split1(acc + bq[o], h, l);
            const size_t qi = ((size_t)b * HW_ + i) * C8_ + o;
            g_qT_hi[qi] = h; g_qT_lo[qi] = l;
        } else if (o < 128) {
            split1(acc + bk[o - 64], h, l);
            const size_t ki = ((size_t)b * HW_ + i) * C8_ + (o - 64);
            g_kT_hi[ki] = h; g_kT_lo[ki] = l;
        } else {
            split1(acc + bv[o - 128], h, l);
            const size_t vi = ((size_t)b * C_ + (o - 128)) * HW_ + i;
            g_v_hi[vi] = h; g_v_lo[vi] = l;
        }
    }
#endif
}

// ---------------------------------------------------------------------------
// Kernel: energy on tcgen05 (bf16x3), N=256 tile, cp.async one-shot loader.
// E[i,j] = sum_c q[i,c] k[j,c]. M=128 (i), N=256 (j), K=64.
// ---------------------------------------------------------------------------
__global__ __launch_bounds__(256) void energy_tc_kernel(float* __restrict__ att)
{
    extern __shared__ char smem[];
    const int tid = threadIdx.x;
    const int b  = blockIdx.z;
    const int m0 = blockIdx.y * 128;   // i
    const int n0 = blockIdx.x * 256;   // j

#if HAS_TCGEN05
    const uint32_t sb = smem_u32(smem);
    const uint32_t SAh = sb + 1024;
    const uint32_t SAl = SAh + TILE_BYTES;
    const uint32_t SBh = SAl + TILE_BYTES;
    const uint32_t SBl = SBh + 32768;

    const __nv_bfloat16* qh = g_qT_hi + ((size_t)b * HW_ + m0) * C8_;
    const __nv_bfloat16* ql = g_qT_lo + ((size_t)b * HW_ + m0) * C8_;
    const __nv_bfloat16* kh = g_kT_hi + ((size_t)b * HW_ + n0) * C8_;
    const __nv_bfloat16* kl = g_kT_lo + ((size_t)b * HW_ + n0) * C8_;

    // A: 128 rows x 128B (hi & lo): 1024 16B-units each
#pragma unroll
    for (int i = 0; i < 4; ++i) {
        const int u = tid + i * 256;
        const int r = u >> 3;
        const int c = (u & 7) * 8;   // bf16 elements
        const uint32_t sw = SMEM_SWIZZLE_128B((uint32_t)(r * 128 + c * 2));
        cp16(SAh + sw, qh + (size_t)r * C8_ + c);
        cp16(SAl + sw, ql + (size_t)r * C8_ + c);
    }
    // B: 256 rows x 128B (hi & lo): 2048 units each
#pragma unroll
    for (int i = 0; i < 8; ++i) {
        const int u = tid + i * 256;
        const int r = u >> 3;
        const int c = (u & 7) * 8;
        const uint32_t sw = SMEM_SWIZZLE_128B((uint32_t)(r * 128 + c * 2));
        cp16(SBh + sw, kh + (size_t)r * C8_ + c);
        cp16(SBl + sw, kl + (size_t)r * C8_ + c);
    }
    cp_commit();

    if (tid < 32) tc_alloc(sb, 256u);
    if (tid == 0) mbar_init(sb + 8, 1);
    __syncthreads();
    const uint32_t tmem = *reinterpret_cast<volatile uint32_t*>(smem);

    asm volatile("cp.async.wait_group 0;" ::: "memory");
    __syncthreads();
    asm volatile("fence.proxy.async.shared::cta;" ::: "memory");

    if (tid < 32 && elect_one_pred()) {
        const uint64_t dAh = make_desc(SAh);
        const uint64_t dAl = make_desc(SAl);
        const uint64_t dBh = make_desc(SBh);
        const uint64_t dBl = make_desc(SBl);
#pragma unroll
        for (int ks = 0; ks < 4; ++ks) {
            mma_f16_ss(tmem, dAh + ks * 2, dBh + ks * 2, IDESC_128x256, ks == 0 ? 0u : 1u);
            mma_f16_ss(tmem, dAh + ks * 2, dBl + ks * 2, IDESC_128x256, 1u);
            mma_f16_ss(tmem, dAl + ks * 2, dBh + ks * 2, IDESC_128x256, 1u);
        }
        tc_commit(sb + 8);
    }
    mbar_wait(sb + 8, 0u);
    asm volatile("tcgen05.fence::after_thread_sync;" ::: "memory");

    if (tid < 128) {
        float* row = att + ((size_t)b * HW_ + m0 + tid) * HW_ + n0;
        for (int cb = 0; cb < 256; cb += 32) {
            uint32_t d[32];
            TCGEN05_LD_32X32B_X32(d, tmem + cb);
            asm volatile("tcgen05.wait::ld.sync.aligned;" ::: "memory");
            float4* dst = reinterpret_cast<float4*>(row + cb);
#pragma unroll
            for (int e = 0; e < 8; ++e)
                dst[e] = make_float4(__uint_as_float(d[4 * e]),     __uint_as_float(d[4 * e + 1]),
                                     __uint_as_float(d[4 * e + 2]), __uint_as_float(d[4 * e + 3]));
        }
    }
    __syncthreads();
    if (tid == 0) mbar_inval(sb + 8);
    if (tid < 32) tc_dealloc(tmem, 256u);
#else
    for (int e = tid; e < 128 * 256; e += 256) {
        const int ml = e >> 8, nl = e & 255;
        float acc = 0.f;
        for (int c = 0; c < C8_; ++c)
            acc += recon(g_qT_hi, g_qT_lo, ((size_t)b * HW_ + m0 + ml) * C8_ + c) *
                   recon(g_kT_hi, g_kT_lo, ((size_t)b * HW_ + n0 + nl) * C8_ + c);
        att[((size_t)b * HW_ + m0 + ml) * HW_ + n0 + nl] = acc;
    }
#endif
}

// ---------------------------------------------------------------------------
// Softmax (in place) + emit att_hi/att_lo bf16 for the out GEMM.
// ---------------------------------------------------------------------------
__global__ __launch_bounds__(256) void softmax_kernel(float* __restrict__ att)
{
    const size_t row = blockIdx.x;
    float4* p = reinterpret_cast<float4*>(att + row * HW_);
    float4 v = p[threadIdx.x];

    __shared__ float red[8];
    const int lid = threadIdx.x & 31;
    const int wid = threadIdx.x >> 5;

    float m = fmaxf(fmaxf(v.x, v.y), fmaxf(v.z, v.w));
#pragma unroll
    for (int off = 16; off; off >>= 1)
        m = fmaxf(m, __shfl_xor_sync(0xFFFFFFFFu, m, off));
    if (lid == 0) red[wid] = m;
    __syncthreads();
    m = red[0];
#pragma unroll
    for (int w = 1; w < 8; ++w) m = fmaxf(m, red[w]);
    __syncthreads();

    v.x = __expf(v.x - m);
    v.y = __expf(v.y - m);
    v.z = __expf(v.z - m);
    v.w = __expf(v.w - m);

    float s = v.x + v.y + v.z + v.w;
#pragma unroll
    for (int off = 16; off; off >>= 1)
        s += __shfl_xor_sync(0xFFFFFFFFu, s, off);
    if (lid == 0) red[wid] = s;
    __syncthreads();
    s = red[0];
#pragma unroll
    for (int w = 1; w < 8; ++w) s += red[w];

    const float inv = 1.0f / s;
    v.x *= inv; v.y *= inv; v.z *= inv; v.w *= inv;
    p[threadIdx.x] = v;

    uint32_t h0, l0, h1, l1;
    split2(v.x, v.y, h0, l0);
    split2(v.z, v.w, h1, l1);
    const size_t e = row * HW_ + (size_t)threadIdx.x * 4;
    *reinterpret_cast<uint2*>(g_att_hi + e) = make_uint2(h0, h1);
    *reinterpret_cast<uint2*>(g_att_lo + e) = make_uint2(l0, l1);
}

// ---------------------------------------------------------------------------
// Kernel: out GEMM on tcgen05 (bf16x3), M=256 (2 m-slices), N=128.
// cp.async prefetch pipeline; direct TMEM->GMEM epilogue.
// D[c,i] = sum_j V[c,j] Att[i,j]; rgb = g*D + x; hha_out = g*D + hha.
// ---------------------------------------------------------------------------
__global__ __launch_bounds__(256)
void out_tc_kernel(const float* __restrict__ x,
                   const float* __restrict__ hha, const float* __restrict__ gamma,
                   float* __restrict__ rgb, float* __restrict__ hhaout)
{
    extern __shared__ char smem[];
    const int tid = threadIdx.x;
    const int b  = blockIdx.z;
    const int m0 = blockIdx.y * 256;   // channels
    const int n0 = blockIdx.x * 128;   // pixels

#if HAS_TCGEN05
    const uint32_t sb = smem_u32(smem);
    const __nv_bfloat16* vh = g_v_hi   + ((size_t)b * C_  + m0) * HW_;  // 256 rows
    const __nv_bfloat16* vl = g_v_lo   + ((size_t)b * C_  + m0) * HW_;
    const __nv_bfloat16* ah = g_att_hi + ((size_t)b * HW_ + n0) * HW_;  // 128 rows
    const __nv_bfloat16* al = g_att_lo + ((size_t)b * HW_ + n0) * HW_;

    // copy chunk (64 j-elements = 128B rows) into stage s
    auto copies = [&](int k, int s) {
        const int k0 = k * 64;
        const uint32_t base = sb + 1024 + s * OUT_STAGE;
        // A: 256 rows hi/lo -> 2048 units each
#pragma unroll
        for (int i = 0; i < 8; ++i) {
            const int u = tid + i * 256;
            const int r = u >> 3;
            const int c = (u & 7) * 8;
            const uint32_t sw = SMEM_SWIZZLE_128B((uint32_t)(r * 128 + c * 2));
            cp16(base + sw,         vh + (size_t)r * HW_ + k0 + c);
            cp16(base + 32768 + sw, vl + (size_t)r * HW_ + k0 + c);
        }
        // B: 128 rows hi/lo -> 1024 units each
#pragma unroll
        for (int i = 0; i < 4; ++i) {
            const int u = tid + i * 256;
            const int r = u >> 3;
            const int c = (u & 7) * 8;
            const uint32_t sw = SMEM_SWIZZLE_128B((uint32_t)(r * 128 + c * 2));
            cp16(base + 65536 + sw, ah + (size_t)r * HW_ + k0 + c);
            cp16(base + 65536 + TILE_BYTES + sw, al + (size_t)r * HW_ + k0 + c);
        }
        cp_commit();
    };

    copies(0, 0);
    if (tid < 32) tc_alloc(sb, 256u);
    if (tid == 0) { mbar_init(sb + 8, 1); mbar_init(sb + 16, 1); }
    __syncthreads();
    const uint32_t tmem = *reinterpret_cast<volatile uint32_t*>(smem);

    for (int k = 0; k < 16; ++k) {
        const int s = k & 1;
        if (k < 15) {
            const int j = k + 1;
            if (j >= 2) mbar_wait(sb + 8 + (j & 1) * 8, (uint32_t)(((j >> 1) - 1) & 1));
            copies(j, j & 1);
        }
        if (k < 15) asm volatile("cp.async.wait_group 1;" ::: "memory");
        else        asm volatile("cp.async.wait_group 0;" ::: "memory");
        __syncthreads();
        asm volatile("fence.proxy.async.shared::cta;" ::: "memory");

        if (tid < 32 && elect_one_pred()) {
            const uint32_t base = sb + 1024 + s * OUT_STAGE;
            const uint64_t dAh = make_desc(base);
            const uint64_t dAl = make_desc(base + 32768);
            const uint64_t dBh = make_desc(base + 65536);
            const uint64_t dBl = make_desc(base + 65536 + TILE_BYTES);
#pragma unroll
            for (int s2 = 0; s2 < 2; ++s2) {
                const uint64_t ao = (uint64_t)s2 * 1024;   // +16KB in 16B units
                const uint32_t dd = tmem + s2 * 128;
#pragma unroll
                for (int ks = 0; ks < 4; ++ks) {
                    const uint32_t en0 = (k == 0 && ks == 0) ? 0u : 1u;
                    mma_f16_ss(dd, dAh + ao + ks * 2, dBh + ks * 2, IDESC_128x128, en0);
                    mma_f16_ss(dd, dAh + ao + ks * 2, dBl + ks * 2, IDESC_128x128, 1u);
                    mma_f16_ss(dd, dAl + ao + ks * 2, dBh + ks * 2, IDESC_128x128, 1u);
                }
            }
            tc_commit(sb + 8 + s * 8);
        }
    }
    mbar_wait(sb + 8, 1u);
    mbar_wait(sb + 16, 1u);
    asm volatile("tcgen05.fence::after_thread_sync;" ::: "memory");
    __syncthreads();

    // Direct epilogue: lane = channel, cols = pixels (contiguous per thread).
    const float g = gamma[0];
    if (tid < 128) {
#pragma unroll
        for (int s2 = 0; s2 < 2; ++s2) {
            const size_t base = ((size_t)b * C_ + m0 + s2 * 128 + tid) * HW_ + n0;
            for (int cb = 0; cb < 128; cb += 32) {
                uint32_t d[32];
                TCGEN05_LD_32X32B_X32(d, tmem + s2 * 128 + cb);
                asm volatile("tcgen05.wait::ld.sync.aligned;" ::: "memory");
#pragma unroll
                for (int e = 0; e < 8; ++e) {
                    const size_t gb = base + cb + e * 4;
                    float4 x4 = *reinterpret_cast<const float4*>(x + gb);
                    float4 h4 = *reinterpret_cast<const float4*>(hha + gb);
                    const float o0 = g * __uint_as_float(d[4 * e]);
                    const float o1 = g * __uint_as_float(d[4 * e + 1]);
                    const float o2 = g * __uint_as_float(d[4 * e + 2]);
                    const float o3 = g * __uint_as_float(d[4 * e + 3]);
                    *reinterpret_cast<float4*>(rgb + gb) =
                        make_float4(o0 + x4.x, o1 + x4.y, o2 + x4.z, o3 + x4.w);
                    *reinterpret_cast<float4*>(hhaout + gb) =
                        make_float4(o0 + h4.x, o1 + h4.y, o2 + h4.z, o3 + h4.w);
                }
            }
        }
    }
    __syncthreads();
    if (tid == 0) { mbar_inval(sb + 8); mbar_inval(sb + 16); }
    if (tid < 32) tc_dealloc(tmem, 256u);
#else
    const float g = gamma[0];
    for (int e = tid; e < 256 * 128; e += 256) {
        const int ml = e >> 7, nl = e & 127;
        float acc = 0.f;
        for (int j = 0; j < HW_; ++j)
            acc += recon(g_v_hi, g_v_lo, ((size_t)b * C_ + m0 + ml) * HW_ + j) *
                   recon(g_att_hi, g_att_lo, ((size_t)b * HW_ + n0 + nl) * HW_ + j);
        const size_t gb = ((size_t)b * C_ + m0 + ml) * HW_ + n0 + nl;
        rgb[gb]    = g * acc + x[gb];
        hhaout[gb] = g * acc + hha[gb];
    }
#endif
}

// ---------------------------------------------------------------------------
extern "C" void kernel_launch(void* const* d_in, const int* in_sizes, int n_in,
                              void* d_out, int out_size)
{
    const float* x     = (const float*)d_in[0];
    const float* hha   = (const float*)d_in[1];
    const float* wq    = (const float*)d_in[2];
    const float* bq    = (const float*)d_in[3];
    const float* wk    = (const float*)d_in[4];
    const float* bk    = (const float*)d_in[5];
    const float* wv    = (const float*)d_in[6];
    const float* bv    = (const float*)d_in[7];
    const float* gamma = (const float*)d_in[8];

    float* att    = (float*)d_out;                         // [32,1024,1024]
    float* rgb    = att + (size_t)B_ * HW_ * HW_;          // [32,512,32,32]
    float* hhaout = rgb + (size_t)B_ * C_ * HW_;           // [32,512,32,32]

    static bool attr_set = false;
    if (!attr_set) {
        cudaFuncSetAttribute(qkv_tc_kernel,    cudaFuncAttributeMaxDynamicSharedMemorySize, QKV_SMEM);
        cudaFuncSetAttribute(energy_tc_kernel, cudaFuncAttributeMaxDynamicSharedMemorySize, EN_SMEM);
        cudaFuncSetAttribute(out_tc_kernel,    cudaFuncAttributeMaxDynamicSharedMemorySize, OUT_SMEM);
        attr_set = true;
    }

    xsplit_kernel   <<<dim3(32, 16, 32), dim3(32, 8)>>>(x);
    wsplit_kernel   <<<WR_ * C_ / 256, 256>>>(wq, wk, wv);
    qkv_tc_kernel   <<<dim3(8, 5, 32), 256, QKV_SMEM>>>(bq, bk, bv);
    energy_tc_kernel<<<dim3(4, 8, 32), 256, EN_SMEM>>>(att);
    softmax_kernel  <<<B_ * HW_, 256>>>(att);
    out_tc_kernel   <<<dim3(8, 2, 32), 256, OUT_SMEM>>>(x, hha, gamma, rgb, hhaout);
}

// round 6
// speedup vs baseline: 3.4994x; 1.1667x over previous
#include <cuda_runtime.h>
#include <cuda_bf16.h>
#include <cstdint>

#define B_    32
#define C_    512
#define HW_   1024
#define C8_   64
#define WR_   640     // 64 q + 64 k + 512 v rows

#if defined(__CUDA_ARCH__) && defined(__CUDA_ARCH_FEAT_SM103_ALL)
#define HAS_TCGEN05 1
#else
#define HAS_TCGEN05 0
#endif

// ---------------------------------------------------------------------------
// Scratch (device globals)
// ---------------------------------------------------------------------------
__device__ __nv_bfloat16 g_xT_hi[(size_t)B_ * HW_ * C_];   // [b][i][c]
__device__ __nv_bfloat16 g_xT_lo[(size_t)B_ * HW_ * C_];
__device__ __nv_bfloat16 g_w_hi [(size_t)WR_ * C_];        // [o][c]
__device__ __nv_bfloat16 g_w_lo [(size_t)WR_ * C_];
__device__ __nv_bfloat16 g_qT_hi[(size_t)B_ * HW_ * C8_];  // [b][i][c8]
__device__ __nv_bfloat16 g_qT_lo[(size_t)B_ * HW_ * C8_];
__device__ __nv_bfloat16 g_kT_hi[(size_t)B_ * HW_ * C8_];
__device__ __nv_bfloat16 g_kT_lo[(size_t)B_ * HW_ * C8_];
__device__ __nv_bfloat16 g_v_hi [(size_t)B_ * C_ * HW_];   // [c][j]
__device__ __nv_bfloat16 g_v_lo [(size_t)B_ * C_ * HW_];
__device__ __nv_bfloat16 g_att_hi[(size_t)B_ * HW_ * HW_]; // [i][j]
__device__ __nv_bfloat16 g_att_lo[(size_t)B_ * HW_ * HW_];

// ---------------------------------------------------------------------------
// Helpers
// ---------------------------------------------------------------------------
__device__ __forceinline__ uint32_t smem_u32(const void* p) {
    uint32_t a;
    asm("{ .reg .u64 t; cvta.to.shared.u64 t, %1; cvt.u32.u64 %0, t; }" : "=r"(a) : "l"(p));
    return a;
}
__device__ __forceinline__ uint32_t elect_one_pred() {
    uint32_t p;
    asm volatile("{\n\t.reg .pred p;\n\telect.sync _|p, 0xFFFFFFFF;\n\tselp.b32 %0, 1, 0, p;\n\t}" : "=r"(p));
    return p;
}
#define SMEM_SWIZZLE_128B(off) ((off) ^ (((off) >> 3) & 0x70))

__device__ __forceinline__ void cp16(uint32_t dst, const void* src) {
    asm volatile("cp.async.cg.shared.global [%0], [%1], 16;" :: "r"(dst), "l"(src));
}
__device__ __forceinline__ void cp_commit() {
    asm volatile("cp.async.commit_group;" ::: "memory");
}

// pack two fp32 -> bf16x2 (hi) and residual bf16x2 (lo)
__device__ __forceinline__ void split2(float a, float b, uint32_t& hi, uint32_t& lo) {
    asm("cvt.rn.bf16x2.f32 %0, %1, %2;" : "=r"(hi) : "f"(b), "f"(a));
    float fa = __uint_as_float(hi << 16);
    float fb = __uint_as_float(hi & 0xFFFF0000u);
    asm("cvt.rn.bf16x2.f32 %0, %1, %2;" : "=r"(lo) : "f"(b - fb), "f"(a - fa));
}
__device__ __forceinline__ void split1(float v, __nv_bfloat16& h, __nv_bfloat16& l) {
    h = __float2bfloat16(v);
    l = __float2bfloat16(v - __bfloat162float(h));
}
__device__ __forceinline__ float recon(const __nv_bfloat16* h, const __nv_bfloat16* l, size_t i) {
    return __bfloat162float(h[i]) + __bfloat162float(l[i]);
}

static constexpr uint64_t DESC_BASE_SW128 =
    (uint64_t(2) << 61) | (uint64_t(1) << 46) | (uint64_t(64) << 32) | (uint64_t(1) << 16);
__device__ __forceinline__ uint64_t make_desc(uint32_t addr) {
    return DESC_BASE_SW128 | ((uint64_t)(addr >> 4) & 0x3FFF);
}
__device__ __forceinline__ void mbar_init(uint32_t a, uint32_t cnt) {
    asm volatile("mbarrier.init.shared.b64 [%0], %1;" :: "r"(a), "r"(cnt) : "memory");
}
__device__ __forceinline__ void mbar_inval(uint32_t a) {
    asm volatile("mbarrier.inval.shared.b64 [%0];" :: "r"(a) : "memory");
}
__device__ __forceinline__ void mbar_wait(uint32_t a, uint32_t parity) {
    asm volatile(
        "{\n\t.reg .pred P;\n\t"
        "WL_%=:\n\t"
        "mbarrier.try_wait.parity.acquire.cta.shared::cta.b64 P, [%0], %1, 0x989680;\n\t"
        "@P bra.uni WD_%=;\n\t"
        "bra.uni WL_%=;\n\t"
        "WD_%=:\n\t}"
        :: "r"(a), "r"(parity) : "memory");
}

static constexpr uint32_t IDESC_128x128 =
    (1u << 4) | (1u << 7) | (1u << 10) | ((128u / 8) << 17) | ((128u / 16) << 24);
static constexpr uint32_t IDESC_128x256 =
    (1u << 4) | (1u << 7) | (1u << 10) | ((256u / 8) << 17) | ((128u / 16) << 24);

static constexpr int TILE_BYTES  = 16384;           // 128 rows x 128B
static constexpr int QKV_STAGE   = 4 * TILE_BYTES;  // Ahi,Alo,Bhi,Blo (64KB)
static constexpr int QKV_SMEM    = 1024 + 2 * QKV_STAGE;        // 132096
// Energy: A(q) hi/lo 32KB shared + two B tiles hi/lo 64KB each = 160KB
static constexpr int EN_SMEM     = 1024 + 2 * TILE_BYTES + 4 * 32768;   // 164864
static constexpr int OUT_STAGE   = 2 * 32768 + 2 * TILE_BYTES;  // 96KB
static constexpr int OUT_SMEM    = 1024 + 2 * OUT_STAGE;        // 197632

#if HAS_TCGEN05
__device__ __forceinline__ void mma_f16_ss(uint32_t d, uint64_t da, uint64_t db,
                                           uint32_t idesc, uint32_t en) {
    asm volatile(
        "{\n\t.reg .pred p;\n\tsetp.ne.u32 p, %4, 0;\n\t"
        "tcgen05.mma.cta_group::1.kind::f16 [%0], %1, %2, %3, {%5,%5,%5,%5}, p;\n\t}"
        :: "r"(d), "l"(da), "l"(db), "r"(idesc), "r"(en), "r"(0u) : "memory");
}
__device__ __forceinline__ void tc_commit(uint32_t mbar) {
    asm volatile("tcgen05.commit.cta_group::1.mbarrier::arrive::one.shared::cluster.b64 [%0];"
                 :: "r"(mbar) : "memory");
}
__device__ __forceinline__ void tc_alloc(uint32_t smem_addr, uint32_t cols) {
    asm volatile("tcgen05.alloc.cta_group::1.sync.aligned.shared::cta.b32 [%0], %1;"
                 :: "r"(smem_addr), "r"(cols) : "memory");
}
__device__ __forceinline__ void tc_dealloc(uint32_t tmem, uint32_t cols) {
    asm volatile("tcgen05.relinquish_alloc_permit.cta_group::1.sync.aligned;" ::: "memory");
    asm volatile("tcgen05.dealloc.cta_group::1.sync.aligned.b32 %0, %1;" :: "r"(tmem), "r"(cols));
}
#define TCGEN05_LD_32X32B_X32(r, tmem_addr) \
    asm volatile( \
        "tcgen05.ld.sync.aligned.32x32b.x32.b32 " \
        "{%0, %1, %2, %3, %4, %5, %6, %7, " \
        " %8, %9, %10, %11, %12, %13, %14, %15, " \
        " %16, %17, %18, %19, %20, %21, %22, %23, " \
        " %24, %25, %26, %27, %28, %29, %30, %31}, [%32];" \
        : "=r"((r)[0]),  "=r"((r)[1]),  "=r"((r)[2]),  "=r"((r)[3]), \
          "=r"((r)[4]),  "=r"((r)[5]),  "=r"((r)[6]),  "=r"((r)[7]), \
          "=r"((r)[8]),  "=r"((r)[9]),  "=r"((r)[10]), "=r"((r)[11]), \
          "=r"((r)[12]), "=r"((r)[13]), "=r"((r)[14]), "=r"((r)[15]), \
          "=r"((r)[16]), "=r"((r)[17]), "=r"((r)[18]), "=r"((r)[19]), \
          "=r"((r)[20]), "=r"((r)[21]), "=r"((r)[22]), "=r"((r)[23]), \
          "=r"((r)[24]), "=r"((r)[25]), "=r"((r)[26]), "=r"((r)[27]), \
          "=r"((r)[28]), "=r"((r)[29]), "=r"((r)[30]), "=r"((r)[31]) \
        : "r"(tmem_addr))
#endif

// ---------------------------------------------------------------------------
// Prep 1: transpose + split x [b][c][i] fp32 -> xT_hi/lo [b][i][c] bf16
// ---------------------------------------------------------------------------
__global__ void xsplit_kernel(const float* __restrict__ x)
{
    __shared__ float t[32][33];
    const int b  = blockIdx.z;
    const int i0 = blockIdx.x * 32;
    const int c0 = blockIdx.y * 32;
    const int tx = threadIdx.x, ty = threadIdx.y;

#pragma unroll
    for (int j = 0; j < 4; ++j)
        t[ty + 8 * j][tx] = x[((size_t)b * C_ + c0 + ty + 8 * j) * HW_ + i0 + tx];
    __syncthreads();
#pragma unroll
    for (int j = 0; j < 4; ++j) {
        const int c = c0 + tx;
        const int i = i0 + ty + 8 * j;
        const float f = t[tx][ty + 8 * j];
        __nv_bfloat16 h, l;
        split1(f, h, l);
        const size_t idx = ((size_t)b * HW_ + i) * C_ + c;
        g_xT_hi[idx] = h;
        g_xT_lo[idx] = l;
    }
}

// ---------------------------------------------------------------------------
// Prep 2: split weights into combined [640][512] bf16 hi/lo
// ---------------------------------------------------------------------------
__global__ void wsplit_kernel(const float* __restrict__ wq,
                              const float* __restrict__ wk,
                              const float* __restrict__ wv)
{
    const int idx = blockIdx.x * 256 + threadIdx.x;   // < 640*512
    const int o = idx >> 9;
    const int c = idx & 511;
    float v;
    if (o < 64)        v = wq[(size_t)o * C_ + c];
    else if (o < 128)  v = wk[(size_t)(o - 64) * C_ + c];
    else               v = wv[(size_t)(o - 128) * C_ + c];
    __nv_bfloat16 h, l;
    split1(v, h, l);
    g_w_hi[idx] = h;
    g_w_lo[idx] = l;
}

// ---------------------------------------------------------------------------
// Kernel: QKV projection on tcgen05 (bf16x3), cp.async 2-stage prefetch.
// Y[o,i] = sum_c W[o,c] xT[i,c] + bias; M=640 (5 tiles), N=1024, K=512.
// ---------------------------------------------------------------------------
__global__ __launch_bounds__(256) void qkv_tc_kernel(
    const float* __restrict__ bq, const float* __restrict__ bk,
    const float* __restrict__ bv)
{
    extern __shared__ char smem[];
    const int tid = threadIdx.x;
    const int b   = blockIdx.z;
    const int mt  = blockIdx.y;
    const int m0  = mt * 128;
    const int n0  = blockIdx.x * 128;

#if HAS_TCGEN05
    const uint32_t sb = smem_u32(smem);
    const __nv_bfloat16* whb = g_w_hi + (size_t)m0 * C_;
    const __nv_bfloat16* wlb = g_w_lo + (size_t)m0 * C_;
    const __nv_bfloat16* xhb = g_xT_hi + ((size_t)b * HW_ + n0) * C_;
    const __nv_bfloat16* xlb = g_xT_lo + ((size_t)b * HW_ + n0) * C_;

    auto copies = [&](int k, int s) {
        const int k0 = k * 64;
        const uint32_t base = sb + 1024 + s * QKV_STAGE;
#pragma unroll
        for (int i = 0; i < 4; ++i) {
            const int u = tid + i * 256;
            const int r = u >> 3;
            const int c = (u & 7) * 8;
            const uint32_t sw = SMEM_SWIZZLE_128B((uint32_t)(r * 128 + c * 2));
            cp16(base + sw,                  whb + (size_t)r * C_ + k0 + c);
            cp16(base + TILE_BYTES + sw,     wlb + (size_t)r * C_ + k0 + c);
            cp16(base + 2 * TILE_BYTES + sw, xhb + (size_t)r * C_ + k0 + c);
            cp16(base + 3 * TILE_BYTES + sw, xlb + (size_t)r * C_ + k0 + c);
        }
        cp_commit();
    };

    copies(0, 0);
    if (tid < 32) tc_alloc(sb, 128u);
    if (tid == 0) { mbar_init(sb + 8, 1); mbar_init(sb + 16, 1); }
    __syncthreads();
    const uint32_t tmem = *reinterpret_cast<volatile uint32_t*>(smem);

    for (int k = 0; k < 8; ++k) {
        const int s = k & 1;
        if (k < 7) {
            const int j = k + 1;
            if (j >= 2) mbar_wait(sb + 8 + (j & 1) * 8, (uint32_t)(((j >> 1) - 1) & 1));
            copies(j, j & 1);
            asm volatile("cp.async.wait_group 1;" ::: "memory");
        } else {
            asm volatile("cp.async.wait_group 0;" ::: "memory");
        }
        __syncthreads();
        asm volatile("fence.proxy.async.shared::cta;" ::: "memory");

        if (tid < 32 && elect_one_pred()) {
            const uint32_t su = sb + 1024 + s * QKV_STAGE;
            const uint64_t dAh = make_desc(su);
            const uint64_t dAl = make_desc(su + TILE_BYTES);
            const uint64_t dBh = make_desc(su + 2 * TILE_BYTES);
            const uint64_t dBl = make_desc(su + 3 * TILE_BYTES);
#pragma unroll
            for (int ks = 0; ks < 4; ++ks) {
                const uint32_t en0 = (k == 0 && ks == 0) ? 0u : 1u;
                mma_f16_ss(tmem, dAh + ks * 2, dBh + ks * 2, IDESC_128x128, en0);
                mma_f16_ss(tmem, dAh + ks * 2, dBl + ks * 2, IDESC_128x128, 1u);
                mma_f16_ss(tmem, dAl + ks * 2, dBh + ks * 2, IDESC_128x128, 1u);
            }
            tc_commit(sb + 8 + s * 8);
        }
    }
    mbar_wait(sb + 8, 1u);   // 4 commits/stage -> final parity 1
    mbar_wait(sb + 16, 1u);
    asm volatile("tcgen05.fence::after_thread_sync;" ::: "memory");
    __syncthreads();

    if (mt == 0) {
        float* ep = reinterpret_cast<float*>(smem + 1024);
        for (int cb = 0; cb < 128; cb += 32) {
            if (tid < 128) {
                uint32_t d[32];
                TCGEN05_LD_32X32B_X32(d, tmem + cb);
                asm volatile("tcgen05.wait::ld.sync.aligned;" ::: "memory");
                const float bias = (tid < 64) ? bq[tid] : bk[tid - 64];
#pragma unroll
                for (int c = 0; c < 32; ++c)
                    ep[tid * 33 + c] = __uint_as_float(d[c]) + bias;
            }
            __syncthreads();
            const int il = tid >> 3;
            const int ob = (tid & 7) * 8;
            {   // q
                uint32_t hi[4], lo[4];
#pragma unroll
                for (int e = 0; e < 4; ++e)
                    split2(ep[(ob + 2 * e) * 33 + il], ep[(ob + 2 * e + 1) * 33 + il], hi[e], lo[e]);
                const size_t qi = ((size_t)b * HW_ + n0 + cb + il) * C8_ + ob;
                *reinterpret_cast<uint4*>(g_qT_hi + qi) = make_uint4(hi[0], hi[1], hi[2], hi[3]);
                *reinterpret_cast<uint4*>(g_qT_lo + qi) = make_uint4(lo[0], lo[1], lo[2], lo[3]);
            }
            {   // k
                uint32_t hi[4], lo[4];
#pragma unroll
                for (int e = 0; e < 4; ++e)
                    split2(ep[(64 + ob + 2 * e) * 33 + il], ep[(64 + ob + 2 * e + 1) * 33 + il], hi[e], lo[e]);
                const size_t ki = ((size_t)b * HW_ + n0 + cb + il) * C8_ + ob;
                *reinterpret_cast<uint4*>(g_kT_hi + ki) = make_uint4(hi[0], hi[1], hi[2], hi[3]);
                *reinterpret_cast<uint4*>(g_kT_lo + ki) = make_uint4(lo[0], lo[1], lo[2], lo[3]);
            }
            __syncthreads();
        }
    } else {
        if (tid < 128) {
            const int c = m0 - 128 + tid;
            const float bias = bv[c];
            for (int cb = 0; cb < 128; cb += 32) {
                uint32_t d[32];
                TCGEN05_LD_32X32B_X32(d, tmem + cb);
                asm volatile("tcgen05.wait::ld.sync.aligned;" ::: "memory");
                uint32_t hi[16], lo[16];
#pragma unroll
                for (int e = 0; e < 16; ++e)
                    split2(__uint_as_float(d[2 * e]) + bias, __uint_as_float(d[2 * e + 1]) + bias,
                           hi[e], lo[e]);
                const size_t base = ((size_t)b * C_ + c) * HW_ + n0 + cb;
                uint4* dh = reinterpret_cast<uint4*>(g_v_hi + base);
                uint4* dl = reinterpret_cast<uint4*>(g_v_lo + base);
#pragma unroll
                for (int e = 0; e < 4; ++e) {
                    dh[e] = make_uint4(hi[4 * e], hi[4 * e + 1], hi[4 * e + 2], hi[4 * e + 3]);
                    dl[e] = make_uint4(lo[4 * e], lo[4 * e + 1], lo[4 * e + 2], lo[4 * e + 3]);
                }
            }
        }
    }
    __syncthreads();
    if (tid == 0) { mbar_inval(sb + 8); mbar_inval(sb + 16); }
    if (tid < 32) tc_dealloc(tmem, 128u);
#else
    for (int e = tid; e < 128 * 128; e += 256) {
        const int ml = e >> 7, nl = e & 127;
        const int o = m0 + ml, i = n0 + nl;
        float acc = 0.f;
        for (int c = 0; c < C_; ++c)
            acc += recon(g_w_hi, g_w_lo, (size_t)o * C_ + c) *
                   recon(g_xT_hi, g_xT_lo, ((size_t)b * HW_ + i) * C_ + c);
        __nv_bfloat16 h, l;
        if (o < 64) {
            split1(acc + bq[o], h, l);
            const size_t qi = ((size_t)b * HW_ + i) * C8_ + o;
            g_qT_hi[qi] = h; g_qT_lo[qi] = l;
        } else if (o < 128) {
            split1(acc + bk[o - 64], h, l);
            const size_t ki = ((size_t)b * HW_ + i) * C8_ + (o - 64);
            g_kT_hi[ki] = h; g_kT_lo[ki] = l;
        } else {
            split1(acc + bv[o - 128], h, l);
            const size_t vi = ((size_t)b * C_ + (o - 128)) * HW_ + i;
            g_v_hi[vi] = h; g_v_lo[vi] = l;
        }
    }
#endif
}

// ---------------------------------------------------------------------------
// Kernel: energy on tcgen05 (bf16x3). Two N=256 tiles per CTA sharing the
// A (q) tile; both loads issued before TMEM alloc; MMA t1 overlaps epi t0.
// E[i,j] = sum_c q[i,c] k[j,c]. M=128 (i), per-CTA N=512 (j).
// ---------------------------------------------------------------------------
__global__ __launch_bounds__(256) void energy_tc_kernel(float* __restrict__ att)
{
    extern __shared__ char smem[];
    const int tid = threadIdx.x;
    const int b  = blockIdx.z;
    const int m0 = blockIdx.y * 128;   // i
    const int n0 = blockIdx.x * 512;   // j

#if HAS_TCGEN05
    const uint32_t sb  = smem_u32(smem);
    const uint32_t SAh = sb + 1024;
    const uint32_t SAl = SAh + TILE_BYTES;
    const uint32_t SB0h = SAl + TILE_BYTES;
    const uint32_t SB0l = SB0h + 32768;
    const uint32_t SB1h = SB0l + 32768;
    const uint32_t SB1l = SB1h + 32768;

    const __nv_bfloat16* qh = g_qT_hi + ((size_t)b * HW_ + m0) * C8_;
    const __nv_bfloat16* ql = g_qT_lo + ((size_t)b * HW_ + m0) * C8_;
    const __nv_bfloat16* kh = g_kT_hi + ((size_t)b * HW_ + n0) * C8_;
    const __nv_bfloat16* kl = g_kT_lo + ((size_t)b * HW_ + n0) * C8_;

    // group 0: A + B0
#pragma unroll
    for (int i = 0; i < 4; ++i) {
        const int u = tid + i * 256;
        const int r = u >> 3;
        const int c = (u & 7) * 8;
        const uint32_t sw = SMEM_SWIZZLE_128B((uint32_t)(r * 128 + c * 2));
        cp16(SAh + sw, qh + (size_t)r * C8_ + c);
        cp16(SAl + sw, ql + (size_t)r * C8_ + c);
    }
#pragma unroll
    for (int i = 0; i < 8; ++i) {
        const int u = tid + i * 256;
        const int r = u >> 3;
        const int c = (u & 7) * 8;
        const uint32_t sw = SMEM_SWIZZLE_128B((uint32_t)(r * 128 + c * 2));
        cp16(SB0h + sw, kh + (size_t)r * C8_ + c);
        cp16(SB0l + sw, kl + (size_t)r * C8_ + c);
    }
    cp_commit();
    // group 1: B1 (rows 256..511)
#pragma unroll
    for (int i = 0; i < 8; ++i) {
        const int u = tid + i * 256;
        const int r = (u >> 3) + 256;
        const int c = (u & 7) * 8;
        const uint32_t sw = SMEM_SWIZZLE_128B((uint32_t)((r - 256) * 128 + c * 2));
        cp16(SB1h + sw, kh + (size_t)r * C8_ + c);
        cp16(SB1l + sw, kl + (size_t)r * C8_ + c);
    }
    cp_commit();

    if (tid < 32) tc_alloc(sb, 512u);
    if (tid == 0) { mbar_init(sb + 8, 1); mbar_init(sb + 16, 1); }
    __syncthreads();
    const uint32_t tmem = *reinterpret_cast<volatile uint32_t*>(smem);

    const uint64_t dAh = make_desc(SAh);
    const uint64_t dAl = make_desc(SAl);

    // tile 0
    asm volatile("cp.async.wait_group 1;" ::: "memory");
    __syncthreads();
    asm volatile("fence.proxy.async.shared::cta;" ::: "memory");
    if (tid < 32 && elect_one_pred()) {
        const uint64_t dBh = make_desc(SB0h);
        const uint64_t dBl = make_desc(SB0l);
#pragma unroll
        for (int ks = 0; ks < 4; ++ks) {
            mma_f16_ss(tmem, dAh + ks * 2, dBh + ks * 2, IDESC_128x256, ks == 0 ? 0u : 1u);
            mma_f16_ss(tmem, dAh + ks * 2, dBl + ks * 2, IDESC_128x256, 1u);
            mma_f16_ss(tmem, dAl + ks * 2, dBh + ks * 2, IDESC_128x256, 1u);
        }
        tc_commit(sb + 8);
    }
    // tile 1
    asm volatile("cp.async.wait_group 0;" ::: "memory");
    __syncthreads();
    asm volatile("fence.proxy.async.shared::cta;" ::: "memory");
    if (tid < 32 && elect_one_pred()) {
        const uint64_t dBh = make_desc(SB1h);
        const uint64_t dBl = make_desc(SB1l);
#pragma unroll
        for (int ks = 0; ks < 4; ++ks) {
            mma_f16_ss(tmem + 256, dAh + ks * 2, dBh + ks * 2, IDESC_128x256, ks == 0 ? 0u : 1u);
            mma_f16_ss(tmem + 256, dAh + ks * 2, dBl + ks * 2, IDESC_128x256, 1u);
            mma_f16_ss(tmem + 256, dAl + ks * 2, dBh + ks * 2, IDESC_128x256, 1u);
        }
        tc_commit(sb + 16);
    }

#pragma unroll
    for (int t = 0; t < 2; ++t) {
        mbar_wait(sb + 8 + t * 8, 0u);
        asm volatile("tcgen05.fence::after_thread_sync;" ::: "memory");
        if (tid < 128) {
            float* row = att + ((size_t)b * HW_ + m0 + tid) * HW_ + n0 + t * 256;
            for (int cb = 0; cb < 256; cb += 32) {
                uint32_t d[32];
                TCGEN05_LD_32X32B_X32(d, tmem + t * 256 + cb);
                asm volatile("tcgen05.wait::ld.sync.aligned;" ::: "memory");
                float4* dst = reinterpret_cast<float4*>(row + cb);
#pragma unroll
                for (int e = 0; e < 8; ++e)
                    dst[e] = make_float4(__uint_as_float(d[4 * e]),     __uint_as_float(d[4 * e + 1]),
                                         __uint_as_float(d[4 * e + 2]), __uint_as_float(d[4 * e + 3]));
            }
        }
    }
    __syncthreads();
    if (tid == 0) { mbar_inval(sb + 8); mbar_inval(sb + 16); }
    if (tid < 32) tc_dealloc(tmem, 512u);
#else
    for (int e = tid; e < 128 * 512; e += 256) {
        const int ml = e >> 9, nl = e & 511;
        float acc = 0.f;
        for (int c = 0; c < C8_; ++c)
            acc += recon(g_qT_hi, g_qT_lo, ((size_t)b * HW_ + m0 + ml) * C8_ + c) *
                   recon(g_kT_hi, g_kT_lo, ((size_t)b * HW_ + n0 + nl) * C8_ + c);
        att[((size_t)b * HW_ + m0 + ml) * HW_ + n0 + nl] = acc;
    }
#endif
}

// ---------------------------------------------------------------------------
// Softmax (in place) + emit att_hi/att_lo bf16 for the out GEMM.
// ---------------------------------------------------------------------------
__global__ __launch_bounds__(256) void softmax_kernel(float* __restrict__ att)
{
    const size_t row = blockIdx.x;
    float4* p = reinterpret_cast<float4*>(att + row * HW_);
    float4 v = p[threadIdx.x];

    __shared__ float red[8];
    const int lid = threadIdx.x & 31;
    const int wid = threadIdx.x >> 5;

    float m = fmaxf(fmaxf(v.x, v.y), fmaxf(v.z, v.w));
#pragma unroll
    for (int off = 16; off; off >>= 1)
        m = fmaxf(m, __shfl_xor_sync(0xFFFFFFFFu, m, off));
    if (lid == 0) red[wid] = m;
    __syncthreads();
    m = red[0];
#pragma unroll
    for (int w = 1; w < 8; ++w) m = fmaxf(m, red[w]);
    __syncthreads();

    v.x = __expf(v.x - m);
    v.y = __expf(v.y - m);
    v.z = __expf(v.z - m);
    v.w = __expf(v.w - m);

    float s = v.x + v.y + v.z + v.w;
#pragma unroll
    for (int off = 16; off; off >>= 1)
        s += __shfl_xor_sync(0xFFFFFFFFu, s, off);
    if (lid == 0) red[wid] = s;
    __syncthreads();
    s = red[0];
#pragma unroll
    for (int w = 1; w < 8; ++w) s += red[w];

    const float inv = 1.0f / s;
    v.x *= inv; v.y *= inv; v.z *= inv; v.w *= inv;
    p[threadIdx.x] = v;

    uint32_t h0, l0, h1, l1;
    split2(v.x, v.y, h0, l0);
    split2(v.z, v.w, h1, l1);
    const size_t e = row * HW_ + (size_t)threadIdx.x * 4;
    *reinterpret_cast<uint2*>(g_att_hi + e) = make_uint2(h0, h1);
    *reinterpret_cast<uint2*>(g_att_lo + e) = make_uint2(l0, l1);
}

// ---------------------------------------------------------------------------
// Kernel: out GEMM on tcgen05 (bf16x3), M=256 (2 m-slices), N=128.
// cp.async prefetch pipeline; direct TMEM->GMEM epilogue.
// D[c,i] = sum_j V[c,j] Att[i,j]; rgb = g*D + x; hha_out = g*D + hha.
// ---------------------------------------------------------------------------
__global__ __launch_bounds__(256)
void out_tc_kernel(const float* __restrict__ x,
                   const float* __restrict__ hha, const float* __restrict__ gamma,
                   float* __restrict__ rgb, float* __restrict__ hhaout)
{
    extern __shared__ char smem[];
    const int tid = threadIdx.x;
    const int b  = blockIdx.z;
    const int m0 = blockIdx.y * 256;   // channels
    const int n0 = blockIdx.x * 128;   // pixels

#if HAS_TCGEN05
    const uint32_t sb = smem_u32(smem);
    const __nv_bfloat16* vh = g_v_hi   + ((size_t)b * C_  + m0) * HW_;  // 256 rows
    const __nv_bfloat16* vl = g_v_lo   + ((size_t)b * C_  + m0) * HW_;
    const __nv_bfloat16* ah = g_att_hi + ((size_t)b * HW_ + n0) * HW_;  // 128 rows
    const __nv_bfloat16* al = g_att_lo + ((size_t)b * HW_ + n0) * HW_;

    auto copies = [&](int k, int s) {
        const int k0 = k * 64;
        const uint32_t base = sb + 1024 + s * OUT_STAGE;
#pragma unroll
        for (int i = 0; i < 8; ++i) {
            const int u = tid + i * 256;
            const int r = u >> 3;
            const int c = (u & 7) * 8;
            const uint32_t sw = SMEM_SWIZZLE_128B((uint32_t)(r * 128 + c * 2));
            cp16(base + sw,         vh + (size_t)r * HW_ + k0 + c);
            cp16(base + 32768 + sw, vl + (size_t)r * HW_ + k0 + c);
        }
#pragma unroll
        for (int i = 0; i < 4; ++i) {
            const int u = tid + i * 256;
            const int r = u >> 3;
            const int c = (u & 7) * 8;
            const uint32_t sw = SMEM_SWIZZLE_128B((uint32_t)(r * 128 + c * 2));
            cp16(base + 65536 + sw, ah + (size_t)r * HW_ + k0 + c);
            cp16(base + 65536 + TILE_BYTES + sw, al + (size_t)r * HW_ + k0 + c);
        }
        cp_commit();
    };

    copies(0, 0);
    if (tid < 32) tc_alloc(sb, 256u);
    if (tid == 0) { mbar_init(sb + 8, 1); mbar_init(sb + 16, 1); }
    __syncthreads();
    const uint32_t tmem = *reinterpret_cast<volatile uint32_t*>(smem);

    for (int k = 0; k < 16; ++k) {
        const int s = k & 1;
        if (k < 15) {
            const int j = k + 1;
            if (j >= 2) mbar_wait(sb + 8 + (j & 1) * 8, (uint32_t)(((j >> 1) - 1) & 1));
            copies(j, j & 1);
            asm volatile("cp.async.wait_group 1;" ::: "memory");
        } else {
            asm volatile("cp.async.wait_group 0;" ::: "memory");
        }
        __syncthreads();
        asm volatile("fence.proxy.async.shared::cta;" ::: "memory");

        if (tid < 32 && elect_one_pred()) {
            const uint32_t base = sb + 1024 + s * OUT_STAGE;
            const uint64_t dAh = make_desc(base);
            const uint64_t dAl = make_desc(base + 32768);
            const uint64_t dBh = make_desc(base + 65536);
            const uint64_t dBl = make_desc(base + 65536 + TILE_BYTES);
#pragma unroll
            for (int s2 = 0; s2 < 2; ++s2) {
                const uint64_t ao = (uint64_t)s2 * 1024;   // +16KB in 16B units
                const uint32_t dd = tmem + s2 * 128;
#pragma unroll
                for (int ks = 0; ks < 4; ++ks) {
                    const uint32_t en0 = (k == 0 && ks == 0) ? 0u : 1u;
                    mma_f16_ss(dd, dAh + ao + ks * 2, dBh + ks * 2, IDESC_128x128, en0);
                    mma_f16_ss(dd, dAh + ao + ks * 2, dBl + ks * 2, IDESC_128x128, 1u);
                    mma_f16_ss(dd, dAl + ao + ks * 2, dBh + ks * 2, IDESC_128x128, 1u);
                }
            }
            tc_commit(sb + 8 + s * 8);
        }
    }
    mbar_wait(sb + 8, 1u);
    mbar_wait(sb + 16, 1u);
    asm volatile("tcgen05.fence::after_thread_sync;" ::: "memory");
    __syncthreads();

    const float g = gamma[0];
    if (tid < 128) {
#pragma unroll
        for (int s2 = 0; s2 < 2; ++s2) {
            const size_t base = ((size_t)b * C_ + m0 + s2 * 128 + tid) * HW_ + n0;
            for (int cb = 0; cb < 128; cb += 32) {
                uint32_t d[32];
                TCGEN05_LD_32X32B_X32(d, tmem + s2 * 128 + cb);
                asm volatile("tcgen05.wait::ld.sync.aligned;" ::: "memory");
#pragma unroll
                for (int e = 0; e < 8; ++e) {
                    const size_t gb = base + cb + e * 4;
                    float4 x4 = *reinterpret_cast<const float4*>(x + gb);
                    float4 h4 = *reinterpret_cast<const float4*>(hha + gb);
                    const float o0 = g * __uint_as_float(d[4 * e]);
                    const float o1 = g * __uint_as_float(d[4 * e + 1]);
                    const float o2 = g * __uint_as_float(d[4 * e + 2]);
                    const float o3 = g * __uint_as_float(d[4 * e + 3]);
                    *reinterpret_cast<float4*>(rgb + gb) =
                        make_float4(o0 + x4.x, o1 + x4.y, o2 + x4.z, o3 + x4.w);
                    *reinterpret_cast<float4*>(hhaout + gb) =
                        make_float4(o0 + h4.x, o1 + h4.y, o2 + h4.z, o3 + h4.w);
                }
            }
        }
    }
    __syncthreads();
    if (tid == 0) { mbar_inval(sb + 8); mbar_inval(sb + 16); }
    if (tid < 32) tc_dealloc(tmem, 256u);
#else
    const float g = gamma[0];
    for (int e = tid; e < 256 * 128; e += 256) {
        const int ml = e >> 7, nl = e & 127;
        float acc = 0.f;
        for (int j = 0; j < HW_; ++j)
            acc += recon(g_v_hi, g_v_lo, ((size_t)b * C_ + m0 + ml) * HW_ + j) *
                   recon(g_att_hi, g_att_lo, ((size_t)b * HW_ + n0 + nl) * HW_ + j);
        const size_t gb = ((size_t)b * C_ + m0 + ml) * HW_ + n0 + nl;
        rgb[gb]    = g * acc + x[gb];
        hhaout[gb] = g * acc + hha[gb];
    }
#endif
}

// ---------------------------------------------------------------------------
extern "C" void kernel_launch(void* const* d_in, const int* in_sizes, int n_in,
                              void* d_out, int out_size)
{
    const float* x     = (const float*)d_in[0];
    const float* hha   = (const float*)d_in[1];
    const float* wq    = (const float*)d_in[2];
    const float* bq    = (const float*)d_in[3];
    const float* wk    = (const float*)d_in[4];
    const float* bk    = (const float*)d_in[5];
    const float* wv    = (const float*)d_in[6];
    const float* bv    = (const float*)d_in[7];
    const float* gamma = (const float*)d_in[8];

    float* att    = (float*)d_out;                         // [32,1024,1024]
    float* rgb    = att + (size_t)B_ * HW_ * HW_;          // [32,512,32,32]
    float* hhaout = rgb + (size_t)B_ * C_ * HW_;           // [32,512,32,32]

    static bool attr_set = false;
    if (!attr_set) {
        cudaFuncSetAttribute(qkv_tc_kernel,    cudaFuncAttributeMaxDynamicSharedMemorySize, QKV_SMEM);
        cudaFuncSetAttribute(energy_tc_kernel, cudaFuncAttributeMaxDynamicSharedMemorySize, EN_SMEM);
        cudaFuncSetAttribute(out_tc_kernel,    cudaFuncAttributeMaxDynamicSharedMemorySize, OUT_SMEM);
        attr_set = true;
    }

    xsplit_kernel   <<<dim3(32, 16, 32), dim3(32, 8)>>>(x);
    wsplit_kernel   <<<WR_ * C_ / 256, 256>>>(wq, wk, wv);
    qkv_tc_kernel   <<<dim3(8, 5, 32), 256, QKV_SMEM>>>(bq, bk, bv);
    energy_tc_kernel<<<dim3(2, 8, 32), 256, EN_SMEM>>>(att);
    softmax_kernel  <<<B_ * HW_, 256>>>(att);
    out_tc_kernel   <<<dim3(8, 2, 32), 256, OUT_SMEM>>>(x, hha, gamma, rgb, hhaout);
}